// round 2
// baseline (speedup 1.0000x reference)
#include <cuda_runtime.h>
#include <cuda_bf16.h>
#include <cstdint>

// Problem constants (fixed shapes per reference)
#define NN 100000
#define NE 1600000
#define NP 500000
#define DD 128

// Scratch (device globals: allocation-free rule)
__device__ float g_bufA[(size_t)NN * DD];  // 51.2 MB
__device__ float g_bufB[(size_t)NN * DD];  // 51.2 MB
__device__ int   g_deg[NN];
__device__ float g_dinv[NN];

// ---------------------------------------------------------------------------
// Degree / normalization
// ---------------------------------------------------------------------------
__global__ void init_deg_k(int* __restrict__ deg) {
    int i = blockIdx.x * blockDim.x + threadIdx.x;
    if (i < NN) deg[i] = 1;  // self loop
}

__global__ void count_deg_k(const int* __restrict__ dst, int* __restrict__ deg) {
    int i = blockIdx.x * blockDim.x + threadIdx.x;
    int stride = gridDim.x * blockDim.x;
    for (int e = i; e < NE; e += stride)
        atomicAdd(&deg[dst[e]], 1);
}

__global__ void dinv_k(const int* __restrict__ deg, float* __restrict__ dinv) {
    int i = blockIdx.x * blockDim.x + threadIdx.x;
    if (i < NN) dinv[i] = rsqrtf((float)deg[i]);
}

// ---------------------------------------------------------------------------
// GEMM: OUT[N,128] = f(X)[N,128] @ W[128,128]
// TRANS=true applies f(x) = relu(x + bias_in) to input rows (layer-1 epilogue
// fused into layer-2 GEMM input path).
// One thread per output column; W column held in 128 registers; x rows staged
// 8-at-a-time through smem; 4 independent FMA chains for ILP.
// ---------------------------------------------------------------------------
template <bool TRANS>
__global__ void __launch_bounds__(128) gemm_k(const float* __restrict__ X,
                                              const float* __restrict__ W,
                                              const float* __restrict__ bias_in,
                                              float* __restrict__ OUT,
                                              int nrows) {
    const int c = threadIdx.x;  // output column 0..127
    float w[128];
#pragma unroll
    for (int k = 0; k < 128; k++) w[k] = W[k * 128 + c];

    __shared__ float xs[8][128];

    float4 bv = make_float4(0.f, 0.f, 0.f, 0.f);
    if (TRANS) bv = reinterpret_cast<const float4*>(bias_in)[c & 31];

    int r0 = blockIdx.x * 128;
    int rend = min(r0 + 128, nrows);  // NN % 8 == 0, so chunks are always full
    for (int r = r0; r < rend; r += 8) {
        const float4* Xv = reinterpret_cast<const float4*>(X + (size_t)r * 128);
        float4 t0 = Xv[c];
        float4 t1 = Xv[c + 128];
        if (TRANS) {
            t0.x = fmaxf(t0.x + bv.x, 0.f); t0.y = fmaxf(t0.y + bv.y, 0.f);
            t0.z = fmaxf(t0.z + bv.z, 0.f); t0.w = fmaxf(t0.w + bv.w, 0.f);
            t1.x = fmaxf(t1.x + bv.x, 0.f); t1.y = fmaxf(t1.y + bv.y, 0.f);
            t1.z = fmaxf(t1.z + bv.z, 0.f); t1.w = fmaxf(t1.w + bv.w, 0.f);
        }
        reinterpret_cast<float4*>(&xs[0][0])[c] = t0;
        reinterpret_cast<float4*>(&xs[0][0])[c + 128] = t1;
        __syncthreads();

#pragma unroll
        for (int rr = 0; rr < 8; rr += 4) {
            float a0 = 0.f, a1 = 0.f, a2 = 0.f, a3 = 0.f;
#pragma unroll
            for (int k = 0; k < 128; k++) {
                float wk = w[k];
                a0 = fmaf(xs[rr + 0][k], wk, a0);
                a1 = fmaf(xs[rr + 1][k], wk, a1);
                a2 = fmaf(xs[rr + 2][k], wk, a2);
                a3 = fmaf(xs[rr + 3][k], wk, a3);
            }
            OUT[(size_t)(r + rr + 0) * 128 + c] = a0;
            OUT[(size_t)(r + rr + 1) * 128 + c] = a1;
            OUT[(size_t)(r + rr + 2) * 128 + c] = a2;
            OUT[(size_t)(r + rr + 3) * 128 + c] = a3;
        }
        __syncthreads();
    }
}

// ---------------------------------------------------------------------------
// Self-loop init: AGG[i][:] = H[i][:] * dinv[i]^2   (also zero-initializes AGG)
// ---------------------------------------------------------------------------
__global__ void selfloop_k(const float* __restrict__ H,
                           const float* __restrict__ dinv,
                           float* __restrict__ AGG) {
    const int total = NN * 32;  // float4 count
    int idx = blockIdx.x * blockDim.x + threadIdx.x;
    int stride = gridDim.x * blockDim.x;
    for (; idx < total; idx += stride) {
        int node = idx >> 5;
        float s = dinv[node];
        s = s * s;
        float4 v = reinterpret_cast<const float4*>(H)[idx];
        v.x *= s; v.y *= s; v.z *= s; v.w *= s;
        reinterpret_cast<float4*>(AGG)[idx] = v;
    }
}

// ---------------------------------------------------------------------------
// Edge scatter: AGG[dst] += H[src] * dinv[src]*dinv[dst]
// Warp per edge, lane handles one float4, red.global.add.v4.f32 (no return).
// ---------------------------------------------------------------------------
__global__ void scatter_k(const float* __restrict__ H,
                          const int* __restrict__ src,
                          const int* __restrict__ dst,
                          const float* __restrict__ dinv,
                          float* __restrict__ AGG) {
    int gtid = blockIdx.x * blockDim.x + threadIdx.x;
    int lane = gtid & 31;
    int warp = gtid >> 5;
    int nwarps = (gridDim.x * blockDim.x) >> 5;
    for (int e = warp; e < NE; e += nwarps) {
        int s = src[e];
        int d = dst[e];
        float nm = dinv[s] * dinv[d];
        float4 v = reinterpret_cast<const float4*>(H + (size_t)s * 128)[lane];
        float* p = AGG + (size_t)d * 128 + lane * 4;
        asm volatile("red.global.add.v4.f32 [%0], {%1, %2, %3, %4};"
                     :: "l"(p), "f"(v.x * nm), "f"(v.y * nm),
                        "f"(v.z * nm), "f"(v.w * nm)
                     : "memory");
    }
}

// ---------------------------------------------------------------------------
// Pair dot products: out[p] = dot(AGG2[a]+b2, AGG2[b]+b2)
// Warp per pair; first NP from edges, rest from edges_neg.
// ---------------------------------------------------------------------------
__global__ void pairs_k(const float* __restrict__ H,
                        const float* __restrict__ b2,
                        const int* __restrict__ ep,
                        const int* __restrict__ en,
                        float* __restrict__ out) {
    int gtid = blockIdx.x * blockDim.x + threadIdx.x;
    int lane = gtid & 31;
    int warp = gtid >> 5;
    int nwarps = (gridDim.x * blockDim.x) >> 5;
    const int total = 2 * NP;
    float4 bv = reinterpret_cast<const float4*>(b2)[lane];
    for (int p = warp; p < total; p += nwarps) {
        const int* e = (p < NP) ? (ep + 2 * (size_t)p)
                                : (en + 2 * (size_t)(p - NP));
        int a = e[0];
        int b = e[1];
        float4 va = reinterpret_cast<const float4*>(H + (size_t)a * 128)[lane];
        float4 vb = reinterpret_cast<const float4*>(H + (size_t)b * 128)[lane];
        va.x += bv.x; va.y += bv.y; va.z += bv.z; va.w += bv.w;
        vb.x += bv.x; vb.y += bv.y; vb.z += bv.z; vb.w += bv.w;
        float sum = va.x * vb.x + va.y * vb.y + va.z * vb.z + va.w * vb.w;
#pragma unroll
        for (int o = 16; o; o >>= 1)
            sum += __shfl_xor_sync(0xffffffffu, sum, o);
        if (lane == 0) out[p] = sum;
    }
}

// ---------------------------------------------------------------------------
// Launch
// ---------------------------------------------------------------------------
extern "C" void kernel_launch(void* const* d_in, const int* in_sizes, int n_in,
                              void* d_out, int out_size) {
    const float* x  = (const float*)d_in[0];
    const float* W1 = (const float*)d_in[1];
    const float* b1 = (const float*)d_in[2];
    const float* W2 = (const float*)d_in[3];
    const float* b2 = (const float*)d_in[4];
    const int* edge_index = (const int*)d_in[5];
    const int* edges      = (const int*)d_in[6];
    const int* edges_neg  = (const int*)d_in[7];
    float* out = (float*)d_out;

    const int* src = edge_index;
    const int* dst = edge_index + NE;

    float *bufA, *bufB, *dinv;
    int* deg;
    cudaGetSymbolAddress((void**)&bufA, g_bufA);
    cudaGetSymbolAddress((void**)&bufB, g_bufB);
    cudaGetSymbolAddress((void**)&deg,  g_deg);
    cudaGetSymbolAddress((void**)&dinv, g_dinv);

    // 1. degree + normalization
    init_deg_k<<<(NN + 255) / 256, 256>>>(deg);
    count_deg_k<<<4096, 256>>>(dst, deg);
    dinv_k<<<(NN + 255) / 256, 256>>>(deg, dinv);

    const int gemm_grid = (NN + 127) / 128;

    // 2. layer 1: h1 = x @ W1
    gemm_k<false><<<gemm_grid, 128>>>(x, W1, nullptr, bufA, NN);
    // 3. aggregate: agg1 = D^-1/2 A D^-1/2 h1  (self loop + edges)
    selfloop_k<<<4096, 256>>>(bufA, dinv, bufB);
    scatter_k<<<8192, 256>>>(bufA, src, dst, dinv, bufB);

    // 4. layer 2: h2 = relu(agg1 + b1) @ W2   (bias+relu fused into GEMM load)
    gemm_k<true><<<gemm_grid, 128>>>(bufB, W2, b1, bufA, NN);
    // 5. aggregate again
    selfloop_k<<<4096, 256>>>(bufA, dinv, bufB);
    scatter_k<<<8192, 256>>>(bufA, src, dst, dinv, bufB);

    // 6. pair dots (b2 added on the fly)
    pairs_k<<<8192, 256>>>(bufB, b2, edges, edges_neg, out);
}

// round 4
// speedup vs baseline: 1.2318x; 1.2318x over previous
#include <cuda_runtime.h>
#include <cuda_bf16.h>
#include <cstdint>

#define NN 100000
#define NE 1600000
#define NP 500000
#define DD 128
#define SCAN_B 512
#define NBLK ((NN + SCAN_B - 1) / SCAN_B)   // 196

// Scratch (device globals: allocation-free rule)
__device__ float g_bufA[(size_t)NN * DD];   // 51.2 MB  (H)
__device__ float g_bufB[(size_t)NN * DD];   // 51.2 MB  (AGG)
__device__ int   g_deg[NN];
__device__ float g_dinv[NN];
__device__ int   g_rowptr[NN + 1];
__device__ int   g_cursor[NN];
__device__ int   g_col[NE];
__device__ int   g_bsum[NBLK];
__device__ int   g_boff[NBLK];

// ---------------------------------------------------------------------------
// Degree / normalization
// ---------------------------------------------------------------------------
__global__ void init_deg_k(int* __restrict__ deg) {
    int i = blockIdx.x * blockDim.x + threadIdx.x;
    if (i < NN) deg[i] = 1;  // self loop
}

__global__ void count_deg_k(const int* __restrict__ dst, int* __restrict__ deg) {
    int i = blockIdx.x * blockDim.x + threadIdx.x;
    int stride = gridDim.x * blockDim.x;
    for (int e = i; e < NE; e += stride)
        atomicAdd(&deg[dst[e]], 1);
}

__global__ void dinv_k(const int* __restrict__ deg, float* __restrict__ dinv) {
    int i = blockIdx.x * blockDim.x + threadIdx.x;
    if (i < NN) dinv[i] = rsqrtf((float)deg[i]);
}

// ---------------------------------------------------------------------------
// CSR build: exclusive scan of (deg-1) -> rowptr, then atomic fill of col[]
// ---------------------------------------------------------------------------
__global__ void scan1_k(const int* __restrict__ deg, int* __restrict__ bsum) {
    __shared__ int s[SCAN_B];
    int t = threadIdx.x;
    int i = blockIdx.x * SCAN_B + t;
    s[t] = (i < NN) ? (deg[i] - 1) : 0;
    __syncthreads();
    for (int off = SCAN_B / 2; off > 0; off >>= 1) {
        if (t < off) s[t] += s[t + off];
        __syncthreads();
    }
    if (t == 0) bsum[blockIdx.x] = s[0];
}

__global__ void scan2_k(const int* __restrict__ bsum, int* __restrict__ boff) {
    __shared__ int s[NBLK];
    int t = threadIdx.x;
    for (int i = t; i < NBLK; i += blockDim.x) s[i] = bsum[i];
    __syncthreads();
    if (t == 0) {
        int run = 0;
        for (int b = 0; b < NBLK; b++) { int v = s[b]; s[b] = run; run += v; }
    }
    __syncthreads();
    for (int i = t; i < NBLK; i += blockDim.x) boff[i] = s[i];
}

__global__ void scan3_k(const int* __restrict__ deg, const int* __restrict__ boff,
                        int* __restrict__ rowptr, int* __restrict__ cursor) {
    __shared__ int s[2][SCAN_B];
    int t = threadIdx.x;
    int i = blockIdx.x * SCAN_B + t;
    int v = (i < NN) ? (deg[i] - 1) : 0;
    s[0][t] = v;
    __syncthreads();
    int pp = 0;
    for (int off = 1; off < SCAN_B; off <<= 1) {
        int nv = s[pp][t] + ((t >= off) ? s[pp][t - off] : 0);
        s[1 - pp][t] = nv;
        pp = 1 - pp;
        __syncthreads();
    }
    if (i < NN) {
        int excl = s[pp][t] - v + boff[blockIdx.x];
        rowptr[i] = excl;
        cursor[i] = excl;
        if (i == NN - 1) rowptr[NN] = excl + v;
    }
}

__global__ void fill_k(const int* __restrict__ src, const int* __restrict__ dst,
                       int* __restrict__ cursor, int* __restrict__ col) {
    int i = blockIdx.x * blockDim.x + threadIdx.x;
    int stride = gridDim.x * blockDim.x;
    for (int e = i; e < NE; e += stride) {
        int d = dst[e];
        int pos = atomicAdd(&cursor[d], 1);
        col[pos] = src[e];
    }
}

// ---------------------------------------------------------------------------
// GEMM: OUT[N,128] = f(X)[N,128] @ W[128,128]  (+ fused self-loop AGG init)
// TRANS=true: f(x) = relu(x + bias_in).  Epilogue writes OUT and
// AGG = dinv^2 * OUT (self-loop message) -- AGG may alias X (in-place safe:
// rows are consumed into smem before the epilogue writes them).
// Inner loop: float4 LDS (1 LDS.128 : 4 FMA) to unbind the shared pipe.
// ---------------------------------------------------------------------------
template <bool TRANS>
__global__ void __launch_bounds__(128) gemm_k(const float* __restrict__ X,
                                              const float* __restrict__ W,
                                              const float* __restrict__ bias_in,
                                              float* __restrict__ OUT,
                                              float* __restrict__ AGG,
                                              const float* __restrict__ dinv,
                                              int nrows) {
    const int c = threadIdx.x;  // output column 0..127
    float4 w4[32];
#pragma unroll
    for (int k4 = 0; k4 < 32; k4++) {
        w4[k4].x = W[(k4 * 4 + 0) * 128 + c];
        w4[k4].y = W[(k4 * 4 + 1) * 128 + c];
        w4[k4].z = W[(k4 * 4 + 2) * 128 + c];
        w4[k4].w = W[(k4 * 4 + 3) * 128 + c];
    }

    __shared__ float4 xs[8][32];

    float4 bv = make_float4(0.f, 0.f, 0.f, 0.f);
    if (TRANS) bv = reinterpret_cast<const float4*>(bias_in)[c & 31];

    int r0 = blockIdx.x * 128;
    int rend = min(r0 + 128, nrows);  // NN % 8 == 0 -> full stages
    for (int r = r0; r < rend; r += 8) {
        const float4* Xv = reinterpret_cast<const float4*>(X + (size_t)r * 128);
        float4 t0 = Xv[c];
        float4 t1 = Xv[c + 128];
        if (TRANS) {
            t0.x = fmaxf(t0.x + bv.x, 0.f); t0.y = fmaxf(t0.y + bv.y, 0.f);
            t0.z = fmaxf(t0.z + bv.z, 0.f); t0.w = fmaxf(t0.w + bv.w, 0.f);
            t1.x = fmaxf(t1.x + bv.x, 0.f); t1.y = fmaxf(t1.y + bv.y, 0.f);
            t1.z = fmaxf(t1.z + bv.z, 0.f); t1.w = fmaxf(t1.w + bv.w, 0.f);
        }
        reinterpret_cast<float4*>(&xs[0][0])[c] = t0;
        reinterpret_cast<float4*>(&xs[0][0])[c + 128] = t1;
        __syncthreads();

#pragma unroll
        for (int rr = 0; rr < 8; rr += 4) {
            float a0 = 0.f, a1 = 0.f, a2 = 0.f, a3 = 0.f;
#pragma unroll
            for (int k4 = 0; k4 < 32; k4++) {
                float4 wv = w4[k4];
                float4 x0 = xs[rr + 0][k4];
                float4 x1 = xs[rr + 1][k4];
                float4 x2 = xs[rr + 2][k4];
                float4 x3 = xs[rr + 3][k4];
                a0 = fmaf(x0.x, wv.x, a0); a0 = fmaf(x0.y, wv.y, a0);
                a0 = fmaf(x0.z, wv.z, a0); a0 = fmaf(x0.w, wv.w, a0);
                a1 = fmaf(x1.x, wv.x, a1); a1 = fmaf(x1.y, wv.y, a1);
                a1 = fmaf(x1.z, wv.z, a1); a1 = fmaf(x1.w, wv.w, a1);
                a2 = fmaf(x2.x, wv.x, a2); a2 = fmaf(x2.y, wv.y, a2);
                a2 = fmaf(x2.z, wv.z, a2); a2 = fmaf(x2.w, wv.w, a2);
                a3 = fmaf(x3.x, wv.x, a3); a3 = fmaf(x3.y, wv.y, a3);
                a3 = fmaf(x3.z, wv.z, a3); a3 = fmaf(x3.w, wv.w, a3);
            }
            float d0 = dinv[r + rr + 0]; d0 *= d0;
            float d1 = dinv[r + rr + 1]; d1 *= d1;
            float d2 = dinv[r + rr + 2]; d2 *= d2;
            float d3 = dinv[r + rr + 3]; d3 *= d3;
            OUT[(size_t)(r + rr + 0) * 128 + c] = a0;
            OUT[(size_t)(r + rr + 1) * 128 + c] = a1;
            OUT[(size_t)(r + rr + 2) * 128 + c] = a2;
            OUT[(size_t)(r + rr + 3) * 128 + c] = a3;
            AGG[(size_t)(r + rr + 0) * 128 + c] = a0 * d0;
            AGG[(size_t)(r + rr + 1) * 128 + c] = a1 * d1;
            AGG[(size_t)(r + rr + 2) * 128 + c] = a2 * d2;
            AGG[(size_t)(r + rr + 3) * 128 + c] = a3 * d3;
        }
        __syncthreads();
    }
}

// ---------------------------------------------------------------------------
// CSR gather aggregation: AGG[n] += sum_{s in in(n)} H[s] * dinv[s]*dinv[n]
// Warp per node, lane handles one float4. No atomics, single write per node.
// ---------------------------------------------------------------------------
__global__ void gather_k(const float* __restrict__ H,
                         const int* __restrict__ rowptr,
                         const int* __restrict__ col,
                         const float* __restrict__ dinv,
                         float* __restrict__ AGG) {
    int gtid = blockIdx.x * blockDim.x + threadIdx.x;
    int lane = gtid & 31;
    int w = gtid >> 5;
    int nw = (gridDim.x * blockDim.x) >> 5;
    for (int n = w; n < NN; n += nw) {
        float4 acc = reinterpret_cast<const float4*>(AGG + (size_t)n * 128)[lane];
        float4 acc2 = make_float4(0.f, 0.f, 0.f, 0.f);
        float dn = dinv[n];
        int j = rowptr[n];
        int end = rowptr[n + 1];
        for (; j + 1 < end; j += 2) {
            int s0 = __ldg(&col[j]);
            int s1 = __ldg(&col[j + 1]);
            float nm0 = dn * __ldg(&dinv[s0]);
            float nm1 = dn * __ldg(&dinv[s1]);
            float4 v0 = reinterpret_cast<const float4*>(H + (size_t)s0 * 128)[lane];
            float4 v1 = reinterpret_cast<const float4*>(H + (size_t)s1 * 128)[lane];
            acc.x  = fmaf(v0.x, nm0, acc.x);  acc.y  = fmaf(v0.y, nm0, acc.y);
            acc.z  = fmaf(v0.z, nm0, acc.z);  acc.w  = fmaf(v0.w, nm0, acc.w);
            acc2.x = fmaf(v1.x, nm1, acc2.x); acc2.y = fmaf(v1.y, nm1, acc2.y);
            acc2.z = fmaf(v1.z, nm1, acc2.z); acc2.w = fmaf(v1.w, nm1, acc2.w);
        }
        if (j < end) {
            int s0 = __ldg(&col[j]);
            float nm0 = dn * __ldg(&dinv[s0]);
            float4 v0 = reinterpret_cast<const float4*>(H + (size_t)s0 * 128)[lane];
            acc.x = fmaf(v0.x, nm0, acc.x); acc.y = fmaf(v0.y, nm0, acc.y);
            acc.z = fmaf(v0.z, nm0, acc.z); acc.w = fmaf(v0.w, nm0, acc.w);
        }
        acc.x += acc2.x; acc.y += acc2.y; acc.z += acc2.z; acc.w += acc2.w;
        reinterpret_cast<float4*>(AGG + (size_t)n * 128)[lane] = acc;
    }
}

// ---------------------------------------------------------------------------
// Pair dot products: out[p] = dot(H[a]+b2, H[b]+b2)
// ---------------------------------------------------------------------------
__global__ void pairs_k(const float* __restrict__ H,
                        const float* __restrict__ b2,
                        const int* __restrict__ ep,
                        const int* __restrict__ en,
                        float* __restrict__ out) {
    int gtid = blockIdx.x * blockDim.x + threadIdx.x;
    int lane = gtid & 31;
    int warp = gtid >> 5;
    int nwarps = (gridDim.x * blockDim.x) >> 5;
    const int total = 2 * NP;
    float4 bv = reinterpret_cast<const float4*>(b2)[lane];
    for (int p = warp; p < total; p += nwarps) {
        const int* e = (p < NP) ? (ep + 2 * (size_t)p)
                                : (en + 2 * (size_t)(p - NP));
        int a = e[0];
        int b = e[1];
        float4 va = reinterpret_cast<const float4*>(H + (size_t)a * 128)[lane];
        float4 vb = reinterpret_cast<const float4*>(H + (size_t)b * 128)[lane];
        va.x += bv.x; va.y += bv.y; va.z += bv.z; va.w += bv.w;
        vb.x += bv.x; vb.y += bv.y; vb.z += bv.z; vb.w += bv.w;
        float sum = va.x * vb.x + va.y * vb.y + va.z * vb.z + va.w * vb.w;
#pragma unroll
        for (int o = 16; o; o >>= 1)
            sum += __shfl_xor_sync(0xffffffffu, sum, o);
        if (lane == 0) out[p] = sum;
    }
}

// ---------------------------------------------------------------------------
// Launch
// ---------------------------------------------------------------------------
extern "C" void kernel_launch(void* const* d_in, const int* in_sizes, int n_in,
                              void* d_out, int out_size) {
    const float* x  = (const float*)d_in[0];
    const float* W1 = (const float*)d_in[1];
    const float* b1 = (const float*)d_in[2];
    const float* W2 = (const float*)d_in[3];
    const float* b2 = (const float*)d_in[4];
    const int* edge_index = (const int*)d_in[5];
    const int* edges      = (const int*)d_in[6];
    const int* edges_neg  = (const int*)d_in[7];
    float* out = (float*)d_out;

    const int* src = edge_index;
    const int* dst = edge_index + NE;

    float *bufA, *bufB, *dinv;
    int *deg, *rowptr, *cursor, *col, *bsum, *boff;
    cudaGetSymbolAddress((void**)&bufA,   g_bufA);
    cudaGetSymbolAddress((void**)&bufB,   g_bufB);
    cudaGetSymbolAddress((void**)&deg,    g_deg);
    cudaGetSymbolAddress((void**)&dinv,   g_dinv);
    cudaGetSymbolAddress((void**)&rowptr, g_rowptr);
    cudaGetSymbolAddress((void**)&cursor, g_cursor);
    cudaGetSymbolAddress((void**)&col,    g_col);
    cudaGetSymbolAddress((void**)&bsum,   g_bsum);
    cudaGetSymbolAddress((void**)&boff,   g_boff);

    // 1. degree + normalization
    init_deg_k<<<(NN + 255) / 256, 256>>>(deg);
    count_deg_k<<<4096, 256>>>(dst, deg);
    dinv_k<<<(NN + 255) / 256, 256>>>(deg, dinv);

    // 2. CSR build (once; shared by both layers)
    scan1_k<<<NBLK, SCAN_B>>>(deg, bsum);
    scan2_k<<<1, 256>>>(bsum, boff);
    scan3_k<<<NBLK, SCAN_B>>>(deg, boff, rowptr, cursor);
    fill_k<<<4096, 256>>>(src, dst, cursor, col);

    const int gemm_grid = (NN + 127) / 128;

    // 3. layer 1: H1 = x @ W1 ; AGG1 = dinv^2 * H1 (self loop)
    gemm_k<false><<<gemm_grid, 128>>>(x, W1, nullptr, bufA, bufB, dinv, NN);
    gather_k<<<12500, 256>>>(bufA, rowptr, col, dinv, bufB);

    // 4. layer 2: H2 = relu(AGG1 + b1) @ W2 ; AGG2 init in-place over bufB
    gemm_k<true><<<gemm_grid, 128>>>(bufB, W2, b1, bufA, bufB, dinv, NN);
    gather_k<<<12500, 256>>>(bufA, rowptr, col, dinv, bufB);

    // 5. pair dots (b2 added on the fly)
    pairs_k<<<8192, 256>>>(bufB, b2, edges, edges_neg, out);
}

// round 7
// speedup vs baseline: 1.4443x; 1.1726x over previous
#include <cuda_runtime.h>
#include <cuda_bf16.h>
#include <cstdint>

#define NN 100000
#define NE 1600000
#define NP 500000
#define DD 128
#define SCAN_B 512
#define NBLK ((NN + SCAN_B - 1) / SCAN_B)   // 196

#define WSTRIDE 136                  // bf16 elems per padded row (272 B)
#define WIMG_HALF (128 * WSTRIDE)    // 17408 elems per hi/lo image
#define WIMG_LAYER (2 * WIMG_HALF)   // 34816 elems (hi+lo) per layer

// Scratch (device globals: allocation-free rule)
__device__ float g_bufA[(size_t)NN * DD];   // 51.2 MB  (H)
__device__ float g_bufB[(size_t)NN * DD];   // 51.2 MB  (AGG)
__device__ int   g_deg[NN];
__device__ float g_dinv[NN];
__device__ int   g_rowptr[NN + 1];
__device__ int   g_cursor[NN];
__device__ int   g_col[NE];
__device__ int   g_bsum[NBLK];
__device__ int   g_boff[NBLK];
__device__ __align__(16) __nv_bfloat16 g_Wimg[2 * WIMG_LAYER];  // 139 KB

// ===========================================================================
// mma.sync / ldmatrix helpers (base ISA, works on compute_103 target)
// ===========================================================================
__device__ __forceinline__ uint32_t smem_u32(const void* p) {
    uint32_t a;
    asm("{ .reg .u64 t; cvta.to.shared.u64 t, %1; cvt.u32.u64 %0, t; }"
        : "=r"(a) : "l"(p));
    return a;
}
__device__ __forceinline__ void ldm_x4(uint32_t& r0, uint32_t& r1,
                                       uint32_t& r2, uint32_t& r3, uint32_t addr) {
    asm volatile("ldmatrix.sync.aligned.m8n8.x4.shared.b16 {%0,%1,%2,%3}, [%4];"
                 : "=r"(r0), "=r"(r1), "=r"(r2), "=r"(r3) : "r"(addr));
}
__device__ __forceinline__ void ldm_x2t(uint32_t& r0, uint32_t& r1, uint32_t addr) {
    asm volatile("ldmatrix.sync.aligned.m8n8.x2.trans.shared.b16 {%0,%1}, [%2];"
                 : "=r"(r0), "=r"(r1) : "r"(addr));
}
__device__ __forceinline__ void mma_bf16(float* c, uint32_t a0, uint32_t a1,
                                         uint32_t a2, uint32_t a3,
                                         uint32_t b0, uint32_t b1) {
    asm volatile(
        "mma.sync.aligned.m16n8k16.row.col.f32.bf16.bf16.f32 "
        "{%0,%1,%2,%3}, {%4,%5,%6,%7}, {%8,%9}, {%0,%1,%2,%3};"
        : "+f"(c[0]), "+f"(c[1]), "+f"(c[2]), "+f"(c[3])
        : "r"(a0), "r"(a1), "r"(a2), "r"(a3), "r"(b0), "r"(b1));
}

// ---------------------------------------------------------------------------
// Degree / normalization
// ---------------------------------------------------------------------------
__global__ void init_deg_k(int* __restrict__ deg) {
    int i = blockIdx.x * blockDim.x + threadIdx.x;
    if (i < NN) deg[i] = 1;  // self loop
}

__global__ void count_deg_k(const int* __restrict__ dst, int* __restrict__ deg) {
    int i = blockIdx.x * blockDim.x + threadIdx.x;
    int stride = gridDim.x * blockDim.x;
    for (int e = i; e < NE; e += stride)
        atomicAdd(&deg[dst[e]], 1);
}

__global__ void dinv_k(const int* __restrict__ deg, float* __restrict__ dinv) {
    int i = blockIdx.x * blockDim.x + threadIdx.x;
    if (i < NN) dinv[i] = rsqrtf((float)deg[i]);
}

// ---------------------------------------------------------------------------
// W split: W[k][n] fp32 -> k-major bf16 images [128][WSTRIDE] hi then lo.
// k-major layout is exactly what ldmatrix.x2.trans wants for the B operand.
// ---------------------------------------------------------------------------
__global__ void wsplit_k(const float* __restrict__ W1, const float* __restrict__ W2,
                         __nv_bfloat16* __restrict__ img) {
    int i = blockIdx.x * blockDim.x + threadIdx.x;
    if (i >= 2 * WIMG_HALF) return;          // 2 layers x (k,n-padded)
    int L = i / WIMG_HALF;
    int rem = i % WIMG_HALF;
    int k = rem / WSTRIDE;
    int n = rem % WSTRIDE;
    const float* W = L ? W2 : W1;
    float v = (n < 128) ? W[k * 128 + n] : 0.f;
    __nv_bfloat16 h = __float2bfloat16(v);
    __nv_bfloat16 l = __float2bfloat16(v - __bfloat162float(h));
    img[(size_t)L * WIMG_LAYER + rem] = h;
    img[(size_t)L * WIMG_LAYER + WIMG_HALF + rem] = l;
}

// ---------------------------------------------------------------------------
// CSR build: exclusive scan of (deg-1) -> rowptr, then atomic fill of col[]
// ---------------------------------------------------------------------------
__global__ void scan1_k(const int* __restrict__ deg, int* __restrict__ bsum) {
    __shared__ int s[SCAN_B];
    int t = threadIdx.x;
    int i = blockIdx.x * SCAN_B + t;
    s[t] = (i < NN) ? (deg[i] - 1) : 0;
    __syncthreads();
    for (int off = SCAN_B / 2; off > 0; off >>= 1) {
        if (t < off) s[t] += s[t + off];
        __syncthreads();
    }
    if (t == 0) bsum[blockIdx.x] = s[0];
}

__global__ void scan2_k(const int* __restrict__ bsum, int* __restrict__ boff) {
    __shared__ int s[NBLK];
    int t = threadIdx.x;
    for (int i = t; i < NBLK; i += blockDim.x) s[i] = bsum[i];
    __syncthreads();
    if (t == 0) {
        int run = 0;
        for (int b = 0; b < NBLK; b++) { int v = s[b]; s[b] = run; run += v; }
    }
    __syncthreads();
    for (int i = t; i < NBLK; i += blockDim.x) boff[i] = s[i];
}

__global__ void scan3_k(const int* __restrict__ deg, const int* __restrict__ boff,
                        int* __restrict__ rowptr, int* __restrict__ cursor) {
    __shared__ int s[2][SCAN_B];
    int t = threadIdx.x;
    int i = blockIdx.x * SCAN_B + t;
    int v = (i < NN) ? (deg[i] - 1) : 0;
    s[0][t] = v;
    __syncthreads();
    int pp = 0;
    for (int off = 1; off < SCAN_B; off <<= 1) {
        int nv = s[pp][t] + ((t >= off) ? s[pp][t - off] : 0);
        s[1 - pp][t] = nv;
        pp = 1 - pp;
        __syncthreads();
    }
    if (i < NN) {
        int excl = s[pp][t] - v + boff[blockIdx.x];
        rowptr[i] = excl;
        cursor[i] = excl;
        if (i == NN - 1) rowptr[NN] = excl + v;
    }
}

__global__ void fill_k(const int* __restrict__ src, const int* __restrict__ dst,
                       int* __restrict__ cursor, int* __restrict__ col) {
    int i = blockIdx.x * blockDim.x + threadIdx.x;
    int stride = gridDim.x * blockDim.x;
    for (int e = i; e < NE; e += stride) {
        int d = dst[e];
        int pos = atomicAdd(&cursor[d], 1);
        col[pos] = src[e];
    }
}

// ---------------------------------------------------------------------------
// Convert 128 fp32 rows -> bf16 A image in smem (row pitch WSTRIDE).
// pass 0: hi split; pass 1: lo residual. TRANS applies relu(x + bias) first.
// 256 threads: thread handles row tid/2, 64-col half tid%2.
// ---------------------------------------------------------------------------
template <bool TRANS>
__device__ __forceinline__ void convert_tile(const float* __restrict__ X,
                                             const float* __restrict__ sbias,
                                             __nv_bfloat16* __restrict__ sA,
                                             int r0, int nrows, int pass) {
    int tid = threadIdx.x;
    int m = tid >> 1;
    int c0 = (tid & 1) << 6;
    long r = (long)r0 + m;
    bool valid = r < nrows;
    const float4* Xv = (const float4*)(X + (size_t)r * 128 + c0);
    const float4* Bv = (const float4*)(sbias + c0);
    uint4* dst = (uint4*)(sA + m * WSTRIDE + c0);
#pragma unroll
    for (int j = 0; j < 8; j++) {
        float4 v0 = make_float4(0.f, 0.f, 0.f, 0.f), v1 = v0;
        if (valid) { v0 = Xv[2 * j]; v1 = Xv[2 * j + 1]; }
        if (TRANS) {
            float4 b0 = Bv[2 * j], b1 = Bv[2 * j + 1];
            v0.x = fmaxf(v0.x + b0.x, 0.f); v0.y = fmaxf(v0.y + b0.y, 0.f);
            v0.z = fmaxf(v0.z + b0.z, 0.f); v0.w = fmaxf(v0.w + b0.w, 0.f);
            v1.x = fmaxf(v1.x + b1.x, 0.f); v1.y = fmaxf(v1.y + b1.y, 0.f);
            v1.z = fmaxf(v1.z + b1.z, 0.f); v1.w = fmaxf(v1.w + b1.w, 0.f);
        }
        float f[8] = {v0.x, v0.y, v0.z, v0.w, v1.x, v1.y, v1.z, v1.w};
        uint32_t pk[4];
#pragma unroll
        for (int q = 0; q < 4; q++) {
            float a = f[2 * q], b = f[2 * q + 1];
            __nv_bfloat16 ha = __float2bfloat16(a);
            __nv_bfloat16 hb = __float2bfloat16(b);
            if (pass) {
                ha = __float2bfloat16(a - __bfloat162float(ha));
                hb = __float2bfloat16(b - __bfloat162float(hb));
            }
            __nv_bfloat162 t;
            t.x = ha; t.y = hb;
            pk[q] = *(uint32_t*)&t;
        }
        dst[j] = make_uint4(pk[0], pk[1], pk[2], pk[3]);
    }
}

// One full K=128 MMA sweep: acc[16 n-tiles] += A(16 rows) x B(128 cols)
__device__ __forceinline__ void mma_pass(uint32_t aLane, uint32_t bLane,
                                         float acc[16][4]) {
#pragma unroll 1
    for (int ks = 0; ks < 8; ks++) {
        uint32_t a0, a1, a2, a3;
        ldm_x4(a0, a1, a2, a3, aLane + ks * 32);
        uint32_t bk = bLane + ks * 16 * (WSTRIDE * 2);
#pragma unroll
        for (int nt = 0; nt < 16; nt++) {
            uint32_t b0, b1;
            ldm_x2t(b0, b1, bk + nt * 16);
            mma_bf16(acc[nt], a0, a1, a2, a3, b0, b1);
        }
    }
}

// ---------------------------------------------------------------------------
// HMMA GEMM: OUT[N,128] = f(X) @ W with fp32 accuracy via 2-way bf16 split
// (D = Ah@Wh + Ah@Wl + Al@Wh). Fused epilogue: OUT and AGG = dinv^2 * OUT.
// AGG may alias X (all X reads precede epilogue writes per block).
// 256 threads / 128-row tile; ~105 KB smem -> 2 CTAs/SM.
// ---------------------------------------------------------------------------
template <bool TRANS>
__global__ void __launch_bounds__(256) gemm_mma_k(const float* __restrict__ X,
                                                  const __nv_bfloat16* __restrict__ Wimg,
                                                  const float* __restrict__ bias_in,
                                                  float* __restrict__ OUT,
                                                  float* __restrict__ AGG,
                                                  const float* __restrict__ dinv,
                                                  int nrows) {
    extern __shared__ __align__(16) unsigned char sm[];
    float* sbias = (float*)sm;                                   // 512 B
    __nv_bfloat16* sW = (__nv_bfloat16*)(sm + 512);              // hi then lo
    __nv_bfloat16* sA = (__nv_bfloat16*)(sm + 512 + 2 * WIMG_HALF * 2);
    int tid = threadIdx.x, wid = tid >> 5, lane = tid & 31;

    if (TRANS && tid < 32)
        ((float4*)sbias)[tid] = ((const float4*)bias_in)[tid];
    for (int i = tid; i < (2 * WIMG_HALF * 2) / 16; i += 256)
        ((uint4*)sW)[i] = ((const uint4*)Wimg)[i];

    int r0 = blockIdx.x * 128;
    convert_tile<TRANS>(X, sbias, sA, r0, nrows, 0);  // A-hi
    __syncthreads();

    float acc[16][4];
#pragma unroll
    for (int nt = 0; nt < 16; nt++)
#pragma unroll
        for (int q = 0; q < 4; q++) acc[nt][q] = 0.f;

    uint32_t aLane = smem_u32(sA) + (wid * 16 + (lane & 15)) * (WSTRIDE * 2)
                   + (lane >> 4) * 16;
    uint32_t bHi = smem_u32(sW) + (lane & 15) * (WSTRIDE * 2);
    uint32_t bLo = bHi + WIMG_HALF * 2;

    mma_pass(aLane, bHi, acc);   // Ah @ Wh
    mma_pass(aLane, bLo, acc);   // Ah @ Wl
    __syncthreads();
    convert_tile<TRANS>(X, sbias, sA, r0, nrows, 1);  // A-lo residual
    __syncthreads();
    mma_pass(aLane, bHi, acc);   // Al @ Wh

    // Epilogue: c-frag (row = lane/4 [+8], col = (lane%3..)*2) -> OUT + AGG
    int row0 = r0 + wid * 16 + (lane >> 2);
    int col = (lane & 3) * 2;
#pragma unroll
    for (int half = 0; half < 2; half++) {
        int row = row0 + half * 8;
        if (row < nrows) {
            float dv = dinv[row], d2 = dv * dv;
            float* po = OUT + (size_t)row * 128 + col;
            float* pa = AGG + (size_t)row * 128 + col;
#pragma unroll
            for (int nt = 0; nt < 16; nt++) {
                float vx = acc[nt][2 * half], vy = acc[nt][2 * half + 1];
                *(float2*)(po + nt * 8) = make_float2(vx, vy);
                *(float2*)(pa + nt * 8) = make_float2(vx * d2, vy * d2);
            }
        }
    }
}

// ---------------------------------------------------------------------------
// CSR gather aggregation: AGG[n] += sum_{s in in(n)} H[s] * dinv[s]*dinv[n]
// ---------------------------------------------------------------------------
__global__ void gather_k(const float* __restrict__ H,
                         const int* __restrict__ rowptr,
                         const int* __restrict__ col,
                         const float* __restrict__ dinv,
                         float* __restrict__ AGG) {
    int gtid = blockIdx.x * blockDim.x + threadIdx.x;
    int lane = gtid & 31;
    int w = gtid >> 5;
    int nw = (gridDim.x * blockDim.x) >> 5;
    for (int n = w; n < NN; n += nw) {
        float4 acc = reinterpret_cast<const float4*>(AGG + (size_t)n * 128)[lane];
        float4 acc2 = make_float4(0.f, 0.f, 0.f, 0.f);
        float dn = dinv[n];
        int j = rowptr[n];
        int end = rowptr[n + 1];
        for (; j + 1 < end; j += 2) {
            int s0 = __ldg(&col[j]);
            int s1 = __ldg(&col[j + 1]);
            float nm0 = dn * __ldg(&dinv[s0]);
            float nm1 = dn * __ldg(&dinv[s1]);
            float4 v0 = reinterpret_cast<const float4*>(H + (size_t)s0 * 128)[lane];
            float4 v1 = reinterpret_cast<const float4*>(H + (size_t)s1 * 128)[lane];
            acc.x  = fmaf(v0.x, nm0, acc.x);  acc.y  = fmaf(v0.y, nm0, acc.y);
            acc.z  = fmaf(v0.z, nm0, acc.z);  acc.w  = fmaf(v0.w, nm0, acc.w);
            acc2.x = fmaf(v1.x, nm1, acc2.x); acc2.y = fmaf(v1.y, nm1, acc2.y);
            acc2.z = fmaf(v1.z, nm1, acc2.z); acc2.w = fmaf(v1.w, nm1, acc2.w);
        }
        if (j < end) {
            int s0 = __ldg(&col[j]);
            float nm0 = dn * __ldg(&dinv[s0]);
            float4 v0 = reinterpret_cast<const float4*>(H + (size_t)s0 * 128)[lane];
            acc.x = fmaf(v0.x, nm0, acc.x); acc.y = fmaf(v0.y, nm0, acc.y);
            acc.z = fmaf(v0.z, nm0, acc.z); acc.w = fmaf(v0.w, nm0, acc.w);
        }
        acc.x += acc2.x; acc.y += acc2.y; acc.z += acc2.z; acc.w += acc2.w;
        reinterpret_cast<float4*>(AGG + (size_t)n * 128)[lane] = acc;
    }
}

// ---------------------------------------------------------------------------
// Pair dot products: out[p] = dot(H[a]+b2, H[b]+b2)
// ---------------------------------------------------------------------------
__global__ void pairs_k(const float* __restrict__ H,
                        const float* __restrict__ b2,
                        const int* __restrict__ ep,
                        const int* __restrict__ en,
                        float* __restrict__ out) {
    int gtid = blockIdx.x * blockDim.x + threadIdx.x;
    int lane = gtid & 31;
    int warp = gtid >> 5;
    int nwarps = (gridDim.x * blockDim.x) >> 5;
    const int total = 2 * NP;
    float4 bv = reinterpret_cast<const float4*>(b2)[lane];
    for (int p = warp; p < total; p += nwarps) {
        const int* e = (p < NP) ? (ep + 2 * (size_t)p)
                                : (en + 2 * (size_t)(p - NP));
        int a = e[0];
        int b = e[1];
        float4 va = reinterpret_cast<const float4*>(H + (size_t)a * 128)[lane];
        float4 vb = reinterpret_cast<const float4*>(H + (size_t)b * 128)[lane];
        va.x += bv.x; va.y += bv.y; va.z += bv.z; va.w += bv.w;
        vb.x += bv.x; vb.y += bv.y; vb.z += bv.z; vb.w += bv.w;
        float sum = va.x * vb.x + va.y * vb.y + va.z * vb.z + va.w * vb.w;
#pragma unroll
        for (int o = 16; o; o >>= 1)
            sum += __shfl_xor_sync(0xffffffffu, sum, o);
        if (lane == 0) out[p] = sum;
    }
}

// ---------------------------------------------------------------------------
// Launch
// ---------------------------------------------------------------------------
extern "C" void kernel_launch(void* const* d_in, const int* in_sizes, int n_in,
                              void* d_out, int out_size) {
    const float* x  = (const float*)d_in[0];
    const float* W1 = (const float*)d_in[1];
    const float* b1 = (const float*)d_in[2];
    const float* W2 = (const float*)d_in[3];
    const float* b2 = (const float*)d_in[4];
    const int* edge_index = (const int*)d_in[5];
    const int* edges      = (const int*)d_in[6];
    const int* edges_neg  = (const int*)d_in[7];
    float* out = (float*)d_out;

    const int* src = edge_index;
    const int* dst = edge_index + NE;

    float *bufA, *bufB, *dinv;
    int *deg, *rowptr, *cursor, *col, *bsum, *boff;
    __nv_bfloat16* wimg;
    cudaGetSymbolAddress((void**)&bufA,   g_bufA);
    cudaGetSymbolAddress((void**)&bufB,   g_bufB);
    cudaGetSymbolAddress((void**)&deg,    g_deg);
    cudaGetSymbolAddress((void**)&dinv,   g_dinv);
    cudaGetSymbolAddress((void**)&rowptr, g_rowptr);
    cudaGetSymbolAddress((void**)&cursor, g_cursor);
    cudaGetSymbolAddress((void**)&col,    g_col);
    cudaGetSymbolAddress((void**)&bsum,   g_bsum);
    cudaGetSymbolAddress((void**)&boff,   g_boff);
    cudaGetSymbolAddress((void**)&wimg,   g_Wimg);

    const int SMEM_MMA = 512 + 2 * WIMG_HALF * 2 + 128 * WSTRIDE * 2;  // 104960
    cudaFuncSetAttribute(gemm_mma_k<false>, cudaFuncAttributeMaxDynamicSharedMemorySize, SMEM_MMA);
    cudaFuncSetAttribute(gemm_mma_k<true>,  cudaFuncAttributeMaxDynamicSharedMemorySize, SMEM_MMA);

    // 1. degree + normalization + W split (independent prep)
    init_deg_k<<<(NN + 255) / 256, 256>>>(deg);
    count_deg_k<<<4096, 256>>>(dst, deg);
    dinv_k<<<(NN + 255) / 256, 256>>>(deg, dinv);
    wsplit_k<<<(2 * WIMG_HALF + 255) / 256, 256>>>(W1, W2, wimg);

    // 2. CSR build (once; shared by both layers)
    scan1_k<<<NBLK, SCAN_B>>>(deg, bsum);
    scan2_k<<<1, 256>>>(bsum, boff);
    scan3_k<<<NBLK, SCAN_B>>>(deg, boff, rowptr, cursor);
    fill_k<<<4096, 256>>>(src, dst, cursor, col);

    const int gemm_grid = (NN + 127) / 128;  // 782

    // 3. layer 1: H1 = x @ W1 ; AGG1 = dinv^2 * H1 (self loop)
    gemm_mma_k<false><<<gemm_grid, 256, SMEM_MMA>>>(x, wimg, nullptr, bufA, bufB, dinv, NN);
    gather_k<<<12500, 256>>>(bufA, rowptr, col, dinv, bufB);

    // 4. layer 2: H2 = relu(AGG1 + b1) @ W2 ; AGG2 init in-place over bufB
    gemm_mma_k<true><<<gemm_grid, 256, SMEM_MMA>>>(bufB, wimg + WIMG_LAYER, b1, bufA, bufB, dinv, NN);
    gather_k<<<12500, 256>>>(bufA, rowptr, col, dinv, bufB);

    // 5. pair dots (b2 added on the fly)
    pairs_k<<<8192, 256>>>(bufB, b2, edges, edges_neg, out);
}

// round 8
// speedup vs baseline: 1.5452x; 1.0698x over previous
#include <cuda_runtime.h>
#include <cuda_bf16.h>
#include <cstdint>

#define NN 100000
#define NE 1600000
#define NP 500000
#define DD 128
#define SCAN_B 512
#define NBLK ((NN + SCAN_B - 1) / SCAN_B)   // 196

#define WSTRIDE 136                  // bf16 elems per padded row (272 B)
#define WIMG_HALF (128 * WSTRIDE)    // 17408 elems per hi/lo image
#define WIMG_LAYER (2 * WIMG_HALF)   // 34816 elems (hi+lo) per layer
#define TILE_M 64

// Scratch (device globals: allocation-free rule)
__device__ float g_bufA[(size_t)NN * DD];   // 51.2 MB  (H)
__device__ float g_bufB[(size_t)NN * DD];   // 51.2 MB  (AGG)
__device__ int   g_deg[NN];
__device__ float g_dinv[NN];
__device__ int   g_rowptr[NN + 1];
__device__ int   g_cursor[NN];
__device__ int   g_col[NE];
__device__ int   g_bsum[NBLK];
__device__ int   g_boff[NBLK];
__device__ __align__(16) __nv_bfloat16 g_Wimg[2 * WIMG_LAYER];  // 139 KB

// ===========================================================================
// mma.sync / ldmatrix helpers (base ISA, works on compute_103 target)
// ===========================================================================
__device__ __forceinline__ uint32_t smem_u32(const void* p) {
    uint32_t a;
    asm("{ .reg .u64 t; cvta.to.shared.u64 t, %1; cvt.u32.u64 %0, t; }"
        : "=r"(a) : "l"(p));
    return a;
}
__device__ __forceinline__ void ldm_x4(uint32_t& r0, uint32_t& r1,
                                       uint32_t& r2, uint32_t& r3, uint32_t addr) {
    asm volatile("ldmatrix.sync.aligned.m8n8.x4.shared.b16 {%0,%1,%2,%3}, [%4];"
                 : "=r"(r0), "=r"(r1), "=r"(r2), "=r"(r3) : "r"(addr));
}
__device__ __forceinline__ void ldm_x2t(uint32_t& r0, uint32_t& r1, uint32_t addr) {
    asm volatile("ldmatrix.sync.aligned.m8n8.x2.trans.shared.b16 {%0,%1}, [%2];"
                 : "=r"(r0), "=r"(r1) : "r"(addr));
}
__device__ __forceinline__ void mma_bf16(float* c, uint32_t a0, uint32_t a1,
                                         uint32_t a2, uint32_t a3,
                                         uint32_t b0, uint32_t b1) {
    asm volatile(
        "mma.sync.aligned.m16n8k16.row.col.f32.bf16.bf16.f32 "
        "{%0,%1,%2,%3}, {%4,%5,%6,%7}, {%8,%9}, {%0,%1,%2,%3};"
        : "+f"(c[0]), "+f"(c[1]), "+f"(c[2]), "+f"(c[3])
        : "r"(a0), "r"(a1), "r"(a2), "r"(a3), "r"(b0), "r"(b1));
}

// ---------------------------------------------------------------------------
// Degree / normalization
// ---------------------------------------------------------------------------
__global__ void init_deg_k(int* __restrict__ deg) {
    int i = blockIdx.x * blockDim.x + threadIdx.x;
    if (i < NN) deg[i] = 1;  // self loop
}

__global__ void count_deg_k(const int* __restrict__ dst, int* __restrict__ deg) {
    int i = blockIdx.x * blockDim.x + threadIdx.x;
    int stride = gridDim.x * blockDim.x;
    for (int e = i; e < NE; e += stride)
        atomicAdd(&deg[dst[e]], 1);
}

__global__ void dinv_k(const int* __restrict__ deg, float* __restrict__ dinv) {
    int i = blockIdx.x * blockDim.x + threadIdx.x;
    if (i < NN) dinv[i] = rsqrtf((float)deg[i]);
}

// ---------------------------------------------------------------------------
// W split: W[k][n] fp32 -> k-major bf16 images [128][WSTRIDE] hi then lo.
// ---------------------------------------------------------------------------
__global__ void wsplit_k(const float* __restrict__ W1, const float* __restrict__ W2,
                         __nv_bfloat16* __restrict__ img) {
    int i = blockIdx.x * blockDim.x + threadIdx.x;
    if (i >= 2 * WIMG_HALF) return;
    int L = i / WIMG_HALF;
    int rem = i % WIMG_HALF;
    int k = rem / WSTRIDE;
    int n = rem % WSTRIDE;
    const float* W = L ? W2 : W1;
    float v = (n < 128) ? W[k * 128 + n] : 0.f;
    __nv_bfloat16 h = __float2bfloat16(v);
    __nv_bfloat16 l = __float2bfloat16(v - __bfloat162float(h));
    img[(size_t)L * WIMG_LAYER + rem] = h;
    img[(size_t)L * WIMG_LAYER + WIMG_HALF + rem] = l;
}

// ---------------------------------------------------------------------------
// CSR build
// ---------------------------------------------------------------------------
__global__ void scan1_k(const int* __restrict__ deg, int* __restrict__ bsum) {
    __shared__ int s[SCAN_B];
    int t = threadIdx.x;
    int i = blockIdx.x * SCAN_B + t;
    s[t] = (i < NN) ? (deg[i] - 1) : 0;
    __syncthreads();
    for (int off = SCAN_B / 2; off > 0; off >>= 1) {
        if (t < off) s[t] += s[t + off];
        __syncthreads();
    }
    if (t == 0) bsum[blockIdx.x] = s[0];
}

__global__ void scan2_k(const int* __restrict__ bsum, int* __restrict__ boff) {
    __shared__ int s[NBLK];
    int t = threadIdx.x;
    for (int i = t; i < NBLK; i += blockDim.x) s[i] = bsum[i];
    __syncthreads();
    if (t == 0) {
        int run = 0;
        for (int b = 0; b < NBLK; b++) { int v = s[b]; s[b] = run; run += v; }
    }
    __syncthreads();
    for (int i = t; i < NBLK; i += blockDim.x) boff[i] = s[i];
}

__global__ void scan3_k(const int* __restrict__ deg, const int* __restrict__ boff,
                        int* __restrict__ rowptr, int* __restrict__ cursor) {
    __shared__ int s[2][SCAN_B];
    int t = threadIdx.x;
    int i = blockIdx.x * SCAN_B + t;
    int v = (i < NN) ? (deg[i] - 1) : 0;
    s[0][t] = v;
    __syncthreads();
    int pp = 0;
    for (int off = 1; off < SCAN_B; off <<= 1) {
        int nv = s[pp][t] + ((t >= off) ? s[pp][t - off] : 0);
        s[1 - pp][t] = nv;
        pp = 1 - pp;
        __syncthreads();
    }
    if (i < NN) {
        int excl = s[pp][t] - v + boff[blockIdx.x];
        rowptr[i] = excl;
        cursor[i] = excl;
        if (i == NN - 1) rowptr[NN] = excl + v;
    }
}

__global__ void fill_k(const int* __restrict__ src, const int* __restrict__ dst,
                       int* __restrict__ cursor, int* __restrict__ col) {
    int i = blockIdx.x * blockDim.x + threadIdx.x;
    int stride = gridDim.x * blockDim.x;
    for (int e = i; e < NE; e += stride) {
        int d = dst[e];
        int pos = atomicAdd(&cursor[d], 1);
        col[pos] = src[e];
    }
}

// ---------------------------------------------------------------------------
// Convert TILE_M fp32 rows -> bf16 hi AND lo images in one pass.
// Thread t: row t/4, 32-col quarter (t%4). TRANS applies relu(x+bias) first.
// ---------------------------------------------------------------------------
template <bool TRANS>
__device__ __forceinline__ void convert_tile64(const float* __restrict__ X,
                                               const float* __restrict__ sbias,
                                               __nv_bfloat16* __restrict__ sAhi,
                                               __nv_bfloat16* __restrict__ sAlo,
                                               int r0, int nrows) {
    int tid = threadIdx.x;
    int m = tid >> 2;
    int c0 = (tid & 3) << 5;
    long r = (long)r0 + m;
    bool valid = r < nrows;
    const float4* Xv = (const float4*)(X + (size_t)r * 128 + c0);
    const float4* Bv = (const float4*)(sbias + c0);
    uint4* dh = (uint4*)(sAhi + m * WSTRIDE + c0);
    uint4* dl = (uint4*)(sAlo + m * WSTRIDE + c0);
#pragma unroll
    for (int j = 0; j < 4; j++) {
        float4 v0 = make_float4(0.f, 0.f, 0.f, 0.f), v1 = v0;
        if (valid) { v0 = Xv[2 * j]; v1 = Xv[2 * j + 1]; }
        if (TRANS) {
            float4 b0 = Bv[2 * j], b1 = Bv[2 * j + 1];
            v0.x = fmaxf(v0.x + b0.x, 0.f); v0.y = fmaxf(v0.y + b0.y, 0.f);
            v0.z = fmaxf(v0.z + b0.z, 0.f); v0.w = fmaxf(v0.w + b0.w, 0.f);
            v1.x = fmaxf(v1.x + b1.x, 0.f); v1.y = fmaxf(v1.y + b1.y, 0.f);
            v1.z = fmaxf(v1.z + b1.z, 0.f); v1.w = fmaxf(v1.w + b1.w, 0.f);
        }
        float f[8] = {v0.x, v0.y, v0.z, v0.w, v1.x, v1.y, v1.z, v1.w};
        uint32_t ph[4], pl[4];
#pragma unroll
        for (int q = 0; q < 4; q++) {
            float a = f[2 * q], b = f[2 * q + 1];
            __nv_bfloat16 ha = __float2bfloat16(a);
            __nv_bfloat16 hb = __float2bfloat16(b);
            __nv_bfloat16 la = __float2bfloat16(a - __bfloat162float(ha));
            __nv_bfloat16 lb = __float2bfloat16(b - __bfloat162float(hb));
            __nv_bfloat162 th; th.x = ha; th.y = hb;
            __nv_bfloat162 tl; tl.x = la; tl.y = lb;
            ph[q] = *(uint32_t*)&th;
            pl[q] = *(uint32_t*)&tl;
        }
        dh[j] = make_uint4(ph[0], ph[1], ph[2], ph[3]);
        dl[j] = make_uint4(pl[0], pl[1], pl[2], pl[3]);
    }
}

// ---------------------------------------------------------------------------
// HMMA GEMM: OUT[N,128] = f(X) @ W via 2-way bf16 split, single X read.
// 256 thr / 64-row tile; warps: mw = wid&3 (16-row m-tile), nh = wid>>2
// (64-col n-half). Merged pass does Ah@Wh + Ah@Wl; second pass Al@Wh.
// Fused epilogue: OUT and AGG = dinv^2 * OUT (AGG may alias X).
// ---------------------------------------------------------------------------
template <bool TRANS>
__global__ void __launch_bounds__(256) gemm_mma_k(const float* __restrict__ X,
                                                  const __nv_bfloat16* __restrict__ Wimg,
                                                  const float* __restrict__ bias_in,
                                                  float* __restrict__ OUT,
                                                  float* __restrict__ AGG,
                                                  const float* __restrict__ dinv,
                                                  int nrows) {
    extern __shared__ __align__(16) unsigned char sm[];
    float* sbias = (float*)sm;                                    // 512 B
    __nv_bfloat16* sW   = (__nv_bfloat16*)(sm + 512);             // hi then lo (69632 B)
    __nv_bfloat16* sAhi = (__nv_bfloat16*)(sm + 512 + 2 * WIMG_HALF * 2);
    __nv_bfloat16* sAlo = sAhi + TILE_M * WSTRIDE;
    int tid = threadIdx.x, wid = tid >> 5, lane = tid & 31;
    int mw = wid & 3, nh = wid >> 2;

    if (TRANS && tid < 32)
        ((float4*)sbias)[tid] = ((const float4*)bias_in)[tid];
    for (int i = tid; i < (2 * WIMG_HALF * 2) / 16; i += 256)
        ((uint4*)sW)[i] = ((const uint4*)Wimg)[i];

    int r0 = blockIdx.x * TILE_M;
    convert_tile64<TRANS>(X, sbias, sAhi, sAlo, r0, nrows);
    __syncthreads();

    float acc[8][4];
#pragma unroll
    for (int nt = 0; nt < 8; nt++)
#pragma unroll
        for (int q = 0; q < 4; q++) acc[nt][q] = 0.f;

    uint32_t aHi = smem_u32(sAhi) + (mw * 16 + (lane & 15)) * (WSTRIDE * 2)
                 + (lane >> 4) * 16;
    uint32_t aLo = aHi + TILE_M * WSTRIDE * 2;
    uint32_t bBase = smem_u32(sW) + (lane & 15) * (WSTRIDE * 2) + nh * 128;

    // Pass A-hi: Ah@Wh + Ah@Wl (one A frag feeds both W halves)
#pragma unroll 1
    for (int ks = 0; ks < 8; ks++) {
        uint32_t a0, a1, a2, a3;
        ldm_x4(a0, a1, a2, a3, aHi + ks * 32);
        uint32_t bk = bBase + ks * 16 * (WSTRIDE * 2);
#pragma unroll
        for (int nt = 0; nt < 8; nt++) {
            uint32_t b0, b1, c0, c1;
            ldm_x2t(b0, b1, bk + nt * 16);
            mma_bf16(acc[nt], a0, a1, a2, a3, b0, b1);
            ldm_x2t(c0, c1, bk + nt * 16 + WIMG_HALF * 2);
            mma_bf16(acc[nt], a0, a1, a2, a3, c0, c1);
        }
    }
    // Pass A-lo: Al@Wh
#pragma unroll 1
    for (int ks = 0; ks < 8; ks++) {
        uint32_t a0, a1, a2, a3;
        ldm_x4(a0, a1, a2, a3, aLo + ks * 32);
        uint32_t bk = bBase + ks * 16 * (WSTRIDE * 2);
#pragma unroll
        for (int nt = 0; nt < 8; nt++) {
            uint32_t b0, b1;
            ldm_x2t(b0, b1, bk + nt * 16);
            mma_bf16(acc[nt], a0, a1, a2, a3, b0, b1);
        }
    }

    // Epilogue
    int row0 = r0 + mw * 16 + (lane >> 2);
    int colb = nh * 64 + (lane & 3) * 2;
#pragma unroll
    for (int half = 0; half < 2; half++) {
        int row = row0 + half * 8;
        if (row < nrows) {
            float dv = dinv[row], d2 = dv * dv;
            float* po = OUT + (size_t)row * 128 + colb;
            float* pa = AGG + (size_t)row * 128 + colb;
#pragma unroll
            for (int nt = 0; nt < 8; nt++) {
                float vx = acc[nt][2 * half], vy = acc[nt][2 * half + 1];
                *(float2*)(po + nt * 8) = make_float2(vx, vy);
                *(float2*)(pa + nt * 8) = make_float2(vx * d2, vy * d2);
            }
        }
    }
}

// ---------------------------------------------------------------------------
// CSR gather aggregation: AGG[n] += sum_{s in in(n)} H[s] * dinv[s]*dinv[n]
// Warp per node, 4-way edge unroll for MLP.
// ---------------------------------------------------------------------------
__global__ void gather_k(const float* __restrict__ H,
                         const int* __restrict__ rowptr,
                         const int* __restrict__ col,
                         const float* __restrict__ dinv,
                         float* __restrict__ AGG) {
    int gtid = blockIdx.x * blockDim.x + threadIdx.x;
    int lane = gtid & 31;
    int w = gtid >> 5;
    int nw = (gridDim.x * blockDim.x) >> 5;
    for (int n = w; n < NN; n += nw) {
        float4 a0 = reinterpret_cast<const float4*>(AGG + (size_t)n * 128)[lane];
        float4 a1 = make_float4(0.f, 0.f, 0.f, 0.f), a2 = a1, a3 = a1;
        float dn = dinv[n];
        int j = rowptr[n];
        int end = rowptr[n + 1];
        for (; j + 3 < end; j += 4) {
            int s0 = __ldg(&col[j]);
            int s1 = __ldg(&col[j + 1]);
            int s2 = __ldg(&col[j + 2]);
            int s3 = __ldg(&col[j + 3]);
            float n0 = dn * __ldg(&dinv[s0]);
            float n1 = dn * __ldg(&dinv[s1]);
            float n2 = dn * __ldg(&dinv[s2]);
            float n3 = dn * __ldg(&dinv[s3]);
            float4 v0 = reinterpret_cast<const float4*>(H + (size_t)s0 * 128)[lane];
            float4 v1 = reinterpret_cast<const float4*>(H + (size_t)s1 * 128)[lane];
            float4 v2 = reinterpret_cast<const float4*>(H + (size_t)s2 * 128)[lane];
            float4 v3 = reinterpret_cast<const float4*>(H + (size_t)s3 * 128)[lane];
            a0.x = fmaf(v0.x, n0, a0.x); a0.y = fmaf(v0.y, n0, a0.y);
            a0.z = fmaf(v0.z, n0, a0.z); a0.w = fmaf(v0.w, n0, a0.w);
            a1.x = fmaf(v1.x, n1, a1.x); a1.y = fmaf(v1.y, n1, a1.y);
            a1.z = fmaf(v1.z, n1, a1.z); a1.w = fmaf(v1.w, n1, a1.w);
            a2.x = fmaf(v2.x, n2, a2.x); a2.y = fmaf(v2.y, n2, a2.y);
            a2.z = fmaf(v2.z, n2, a2.z); a2.w = fmaf(v2.w, n2, a2.w);
            a3.x = fmaf(v3.x, n3, a3.x); a3.y = fmaf(v3.y, n3, a3.y);
            a3.z = fmaf(v3.z, n3, a3.z); a3.w = fmaf(v3.w, n3, a3.w);
        }
        for (; j < end; j++) {
            int s0 = __ldg(&col[j]);
            float n0 = dn * __ldg(&dinv[s0]);
            float4 v0 = reinterpret_cast<const float4*>(H + (size_t)s0 * 128)[lane];
            a0.x = fmaf(v0.x, n0, a0.x); a0.y = fmaf(v0.y, n0, a0.y);
            a0.z = fmaf(v0.z, n0, a0.z); a0.w = fmaf(v0.w, n0, a0.w);
        }
        a0.x += a1.x + a2.x + a3.x;
        a0.y += a1.y + a2.y + a3.y;
        a0.z += a1.z + a2.z + a3.z;
        a0.w += a1.w + a2.w + a3.w;
        reinterpret_cast<float4*>(AGG + (size_t)n * 128)[lane] = a0;
    }
}

// ---------------------------------------------------------------------------
// Pair dot products: out[p] = dot(H[a]+b2, H[b]+b2).  2 pairs per warp iter.
// ---------------------------------------------------------------------------
__global__ void pairs_k(const float* __restrict__ H,
                        const float* __restrict__ b2,
                        const int* __restrict__ ep,
                        const int* __restrict__ en,
                        float* __restrict__ out) {
    int gtid = blockIdx.x * blockDim.x + threadIdx.x;
    int lane = gtid & 31;
    int warp = gtid >> 5;
    int nwarps = (gridDim.x * blockDim.x) >> 5;
    const int total = 2 * NP;
    float4 bv = reinterpret_cast<const float4*>(b2)[lane];
    for (int p = warp * 2; p < total; p += nwarps * 2) {
        const int* e0 = (p < NP) ? (ep + 2 * (size_t)p)
                                 : (en + 2 * (size_t)(p - NP));
        int p1 = p + 1;
        const int* e1 = (p1 < NP) ? (ep + 2 * (size_t)p1)
                                  : (en + 2 * (size_t)(p1 - NP));
        int a = e0[0], b = e0[1];
        int c = e1[0], d = e1[1];
        float4 va = reinterpret_cast<const float4*>(H + (size_t)a * 128)[lane];
        float4 vb = reinterpret_cast<const float4*>(H + (size_t)b * 128)[lane];
        float4 vc = reinterpret_cast<const float4*>(H + (size_t)c * 128)[lane];
        float4 vd = reinterpret_cast<const float4*>(H + (size_t)d * 128)[lane];
        va.x += bv.x; va.y += bv.y; va.z += bv.z; va.w += bv.w;
        vb.x += bv.x; vb.y += bv.y; vb.z += bv.z; vb.w += bv.w;
        vc.x += bv.x; vc.y += bv.y; vc.z += bv.z; vc.w += bv.w;
        vd.x += bv.x; vd.y += bv.y; vd.z += bv.z; vd.w += bv.w;
        float s0 = va.x * vb.x + va.y * vb.y + va.z * vb.z + va.w * vb.w;
        float s1 = vc.x * vd.x + vc.y * vd.y + vc.z * vd.z + vc.w * vd.w;
#pragma unroll
        for (int o = 16; o; o >>= 1) {
            s0 += __shfl_xor_sync(0xffffffffu, s0, o);
            s1 += __shfl_xor_sync(0xffffffffu, s1, o);
        }
        if (lane == 0) { out[p] = s0; out[p1] = s1; }
    }
}

// ---------------------------------------------------------------------------
// Launch
// ---------------------------------------------------------------------------
extern "C" void kernel_launch(void* const* d_in, const int* in_sizes, int n_in,
                              void* d_out, int out_size) {
    const float* x  = (const float*)d_in[0];
    const float* W1 = (const float*)d_in[1];
    const float* b1 = (const float*)d_in[2];
    const float* W2 = (const float*)d_in[3];
    const float* b2 = (const float*)d_in[4];
    const int* edge_index = (const int*)d_in[5];
    const int* edges      = (const int*)d_in[6];
    const int* edges_neg  = (const int*)d_in[7];
    float* out = (float*)d_out;

    const int* src = edge_index;
    const int* dst = edge_index + NE;

    float *bufA, *bufB, *dinv;
    int *deg, *rowptr, *cursor, *col, *bsum, *boff;
    __nv_bfloat16* wimg;
    cudaGetSymbolAddress((void**)&bufA,   g_bufA);
    cudaGetSymbolAddress((void**)&bufB,   g_bufB);
    cudaGetSymbolAddress((void**)&deg,    g_deg);
    cudaGetSymbolAddress((void**)&dinv,   g_dinv);
    cudaGetSymbolAddress((void**)&rowptr, g_rowptr);
    cudaGetSymbolAddress((void**)&cursor, g_cursor);
    cudaGetSymbolAddress((void**)&col,    g_col);
    cudaGetSymbolAddress((void**)&bsum,   g_bsum);
    cudaGetSymbolAddress((void**)&boff,   g_boff);
    cudaGetSymbolAddress((void**)&wimg,   g_Wimg);

    const int SMEM_MMA = 512 + 2 * WIMG_HALF * 2 + 2 * TILE_M * WSTRIDE * 2;  // 104960
    cudaFuncSetAttribute(gemm_mma_k<false>, cudaFuncAttributeMaxDynamicSharedMemorySize, SMEM_MMA);
    cudaFuncSetAttribute(gemm_mma_k<true>,  cudaFuncAttributeMaxDynamicSharedMemorySize, SMEM_MMA);

    // 1. degree + normalization + W split
    init_deg_k<<<(NN + 255) / 256, 256>>>(deg);
    count_deg_k<<<4096, 256>>>(dst, deg);
    dinv_k<<<(NN + 255) / 256, 256>>>(deg, dinv);
    wsplit_k<<<(2 * WIMG_HALF + 255) / 256, 256>>>(W1, W2, wimg);

    // 2. CSR build (once; shared by both layers)
    scan1_k<<<NBLK, SCAN_B>>>(deg, bsum);
    scan2_k<<<1, 256>>>(bsum, boff);
    scan3_k<<<NBLK, SCAN_B>>>(deg, boff, rowptr, cursor);
    fill_k<<<4096, 256>>>(src, dst, cursor, col);

    const int gemm_grid = (NN + TILE_M - 1) / TILE_M;  // 1563

    // 3. layer 1: H1 = x @ W1 ; AGG1 = dinv^2 * H1 (self loop)
    gemm_mma_k<false><<<gemm_grid, 256, SMEM_MMA>>>(x, wimg, nullptr, bufA, bufB, dinv, NN);
    gather_k<<<12500, 256>>>(bufA, rowptr, col, dinv, bufB);

    // 4. layer 2: H2 = relu(AGG1 + b1) @ W2 ; AGG2 init in-place over bufB
    gemm_mma_k<true><<<gemm_grid, 256, SMEM_MMA>>>(bufB, wimg + WIMG_LAYER, b1, bufA, bufB, dinv, NN);
    gather_k<<<12500, 256>>>(bufA, rowptr, col, dinv, bufB);

    // 5. pair dots (b2 added on the fly)
    pairs_k<<<8192, 256>>>(bufB, b2, edges, edges_neg, out);
}

// round 9
// speedup vs baseline: 1.8809x; 1.2173x over previous
#include <cuda_runtime.h>
#include <cuda_bf16.h>
#include <cstdint>

#define NN 100000
#define NE 1600000
#define NP 500000
#define DD 128
#define SCAN_B 512
#define NBLK ((NN + SCAN_B - 1) / SCAN_B)   // 196

#define WSTRIDE 136                  // bf16 elems per padded row (272 B)
#define WIMG_HALF (128 * WSTRIDE)    // 17408 elems per hi/lo image
#define WIMG_LAYER (2 * WIMG_HALF)   // 34816 elems (hi+lo) per layer
#define TILE_M 64
#define GEMM_GRID 296                // 2 CTAs/SM x 148 SMs (persistent)

// Scratch (device globals: allocation-free rule)
__device__ float g_bufA[(size_t)NN * DD];   // 51.2 MB  (H' = dinv*H)
__device__ float g_bufB[(size_t)NN * DD];   // 51.2 MB  (AGG)
__device__ int   g_deg[NN];
__device__ float g_dinv[NN];
__device__ int   g_rowptr[NN + 1];
__device__ int   g_cursor[NN];
__device__ int   g_col[NE];
__device__ int   g_bsum[NBLK];
__device__ int   g_boff[NBLK];
__device__ __align__(16) __nv_bfloat16 g_Wimg[2 * WIMG_LAYER];  // 139 KB

// ===========================================================================
// mma.sync / ldmatrix helpers (base ISA, works on compute_103 target)
// ===========================================================================
__device__ __forceinline__ uint32_t smem_u32(const void* p) {
    uint32_t a;
    asm("{ .reg .u64 t; cvta.to.shared.u64 t, %1; cvt.u32.u64 %0, t; }"
        : "=r"(a) : "l"(p));
    return a;
}
__device__ __forceinline__ void ldm_x4(uint32_t& r0, uint32_t& r1,
                                       uint32_t& r2, uint32_t& r3, uint32_t addr) {
    asm volatile("ldmatrix.sync.aligned.m8n8.x4.shared.b16 {%0,%1,%2,%3}, [%4];"
                 : "=r"(r0), "=r"(r1), "=r"(r2), "=r"(r3) : "r"(addr));
}
__device__ __forceinline__ void ldm_x2t(uint32_t& r0, uint32_t& r1, uint32_t addr) {
    asm volatile("ldmatrix.sync.aligned.m8n8.x2.trans.shared.b16 {%0,%1}, [%2];"
                 : "=r"(r0), "=r"(r1) : "r"(addr));
}
__device__ __forceinline__ void mma_bf16(float* c, uint32_t a0, uint32_t a1,
                                         uint32_t a2, uint32_t a3,
                                         uint32_t b0, uint32_t b1) {
    asm volatile(
        "mma.sync.aligned.m16n8k16.row.col.f32.bf16.bf16.f32 "
        "{%0,%1,%2,%3}, {%4,%5,%6,%7}, {%8,%9}, {%0,%1,%2,%3};"
        : "+f"(c[0]), "+f"(c[1]), "+f"(c[2]), "+f"(c[3])
        : "r"(a0), "r"(a1), "r"(a2), "r"(a3), "r"(b0), "r"(b1));
}

// ---------------------------------------------------------------------------
// Degree / normalization
// ---------------------------------------------------------------------------
__global__ void init_deg_k(int* __restrict__ deg) {
    int i = blockIdx.x * blockDim.x + threadIdx.x;
    if (i < NN) deg[i] = 1;  // self loop
}

__global__ void count_deg_k(const int* __restrict__ dst, int* __restrict__ deg) {
    int i = blockIdx.x * blockDim.x + threadIdx.x;
    int stride = gridDim.x * blockDim.x;
    for (int e = i; e < NE; e += stride)
        atomicAdd(&deg[dst[e]], 1);
}

__global__ void dinv_k(const int* __restrict__ deg, float* __restrict__ dinv) {
    int i = blockIdx.x * blockDim.x + threadIdx.x;
    if (i < NN) dinv[i] = rsqrtf((float)deg[i]);
}

// ---------------------------------------------------------------------------
// W split: W[k][n] fp32 -> k-major bf16 images [128][WSTRIDE] hi then lo.
// ---------------------------------------------------------------------------
__global__ void wsplit_k(const float* __restrict__ W1, const float* __restrict__ W2,
                         __nv_bfloat16* __restrict__ img) {
    int i = blockIdx.x * blockDim.x + threadIdx.x;
    if (i >= 2 * WIMG_HALF) return;
    int L = i / WIMG_HALF;
    int rem = i % WIMG_HALF;
    int k = rem / WSTRIDE;
    int n = rem % WSTRIDE;
    const float* W = L ? W2 : W1;
    float v = (n < 128) ? W[k * 128 + n] : 0.f;
    __nv_bfloat16 h = __float2bfloat16(v);
    __nv_bfloat16 l = __float2bfloat16(v - __bfloat162float(h));
    img[(size_t)L * WIMG_LAYER + rem] = h;
    img[(size_t)L * WIMG_LAYER + WIMG_HALF + rem] = l;
}

// ---------------------------------------------------------------------------
// CSR build
// ---------------------------------------------------------------------------
__global__ void scan1_k(const int* __restrict__ deg, int* __restrict__ bsum) {
    __shared__ int s[SCAN_B];
    int t = threadIdx.x;
    int i = blockIdx.x * SCAN_B + t;
    s[t] = (i < NN) ? (deg[i] - 1) : 0;
    __syncthreads();
    for (int off = SCAN_B / 2; off > 0; off >>= 1) {
        if (t < off) s[t] += s[t + off];
        __syncthreads();
    }
    if (t == 0) bsum[blockIdx.x] = s[0];
}

__global__ void scan2_k(const int* __restrict__ bsum, int* __restrict__ boff) {
    __shared__ int s[NBLK];
    int t = threadIdx.x;
    for (int i = t; i < NBLK; i += blockDim.x) s[i] = bsum[i];
    __syncthreads();
    if (t == 0) {
        int run = 0;
        for (int b = 0; b < NBLK; b++) { int v = s[b]; s[b] = run; run += v; }
    }
    __syncthreads();
    for (int i = t; i < NBLK; i += blockDim.x) boff[i] = s[i];
}

__global__ void scan3_k(const int* __restrict__ deg, const int* __restrict__ boff,
                        int* __restrict__ rowptr, int* __restrict__ cursor) {
    __shared__ int s[2][SCAN_B];
    int t = threadIdx.x;
    int i = blockIdx.x * SCAN_B + t;
    int v = (i < NN) ? (deg[i] - 1) : 0;
    s[0][t] = v;
    __syncthreads();
    int pp = 0;
    for (int off = 1; off < SCAN_B; off <<= 1) {
        int nv = s[pp][t] + ((t >= off) ? s[pp][t - off] : 0);
        s[1 - pp][t] = nv;
        pp = 1 - pp;
        __syncthreads();
    }
    if (i < NN) {
        int excl = s[pp][t] - v + boff[blockIdx.x];
        rowptr[i] = excl;
        cursor[i] = excl;
        if (i == NN - 1) rowptr[NN] = excl + v;
    }
}

__global__ void fill_k(const int* __restrict__ src, const int* __restrict__ dst,
                       int* __restrict__ cursor, int* __restrict__ col) {
    int i = blockIdx.x * blockDim.x + threadIdx.x;
    int stride = gridDim.x * blockDim.x;
    for (int e = i; e < NE; e += stride) {
        int d = dst[e];
        int pos = atomicAdd(&cursor[d], 1);
        col[pos] = src[e];
    }
}

// ---------------------------------------------------------------------------
// Convert TILE_M fp32 rows -> bf16 hi AND lo images in one pass.
// Thread t: row t/4, 32-col quarter (t%4). TRANS applies relu(x+bias) first.
// ---------------------------------------------------------------------------
template <bool TRANS>
__device__ __forceinline__ void convert_tile64(const float* __restrict__ X,
                                               const float* __restrict__ sbias,
                                               __nv_bfloat16* __restrict__ sAhi,
                                               __nv_bfloat16* __restrict__ sAlo,
                                               int r0, int nrows) {
    int tid = threadIdx.x;
    int m = tid >> 2;
    int c0 = (tid & 3) << 5;
    long r = (long)r0 + m;
    bool valid = r < nrows;
    const float4* Xv = (const float4*)(X + (size_t)r * 128 + c0);
    const float4* Bv = (const float4*)(sbias + c0);
    uint4* dh = (uint4*)(sAhi + m * WSTRIDE + c0);
    uint4* dl = (uint4*)(sAlo + m * WSTRIDE + c0);
#pragma unroll
    for (int j = 0; j < 4; j++) {
        float4 v0 = make_float4(0.f, 0.f, 0.f, 0.f), v1 = v0;
        if (valid) { v0 = Xv[2 * j]; v1 = Xv[2 * j + 1]; }
        if (TRANS) {
            float4 b0 = Bv[2 * j], b1 = Bv[2 * j + 1];
            v0.x = fmaxf(v0.x + b0.x, 0.f); v0.y = fmaxf(v0.y + b0.y, 0.f);
            v0.z = fmaxf(v0.z + b0.z, 0.f); v0.w = fmaxf(v0.w + b0.w, 0.f);
            v1.x = fmaxf(v1.x + b1.x, 0.f); v1.y = fmaxf(v1.y + b1.y, 0.f);
            v1.z = fmaxf(v1.z + b1.z, 0.f); v1.w = fmaxf(v1.w + b1.w, 0.f);
        }
        float f[8] = {v0.x, v0.y, v0.z, v0.w, v1.x, v1.y, v1.z, v1.w};
        uint32_t ph[4], pl[4];
#pragma unroll
        for (int q = 0; q < 4; q++) {
            float a = f[2 * q], b = f[2 * q + 1];
            __nv_bfloat16 ha = __float2bfloat16(a);
            __nv_bfloat16 hb = __float2bfloat16(b);
            __nv_bfloat16 la = __float2bfloat16(a - __bfloat162float(ha));
            __nv_bfloat16 lb = __float2bfloat16(b - __bfloat162float(hb));
            __nv_bfloat162 th; th.x = ha; th.y = hb;
            __nv_bfloat162 tl; tl.x = la; tl.y = lb;
            ph[q] = *(uint32_t*)&th;
            pl[q] = *(uint32_t*)&tl;
        }
        dh[j] = make_uint4(ph[0], ph[1], ph[2], ph[3]);
        dl[j] = make_uint4(pl[0], pl[1], pl[2], pl[3]);
    }
}

// ---------------------------------------------------------------------------
// Persistent HMMA GEMM: Hs[N,128] = dinv * (f(X) @ W), 2-way bf16 split.
// W loaded to smem ONCE per block; block loops over 64-row tiles.
// Writes ONLY the pre-scaled H' = dinv*H (aggregation absorbs the scaling:
// AGG[n] = dinv[n] * (sum_s H'[s] + H'[n])).
// ---------------------------------------------------------------------------
template <bool TRANS>
__global__ void __launch_bounds__(256) gemm_mma_k(const float* __restrict__ X,
                                                  const __nv_bfloat16* __restrict__ Wimg,
                                                  const float* __restrict__ bias_in,
                                                  float* __restrict__ Hs,
                                                  const float* __restrict__ dinv,
                                                  int nrows, int ntiles) {
    extern __shared__ __align__(16) unsigned char sm[];
    float* sbias = (float*)sm;                                    // 512 B
    __nv_bfloat16* sW   = (__nv_bfloat16*)(sm + 512);             // hi then lo
    __nv_bfloat16* sAhi = (__nv_bfloat16*)(sm + 512 + 2 * WIMG_HALF * 2);
    __nv_bfloat16* sAlo = sAhi + TILE_M * WSTRIDE;
    int tid = threadIdx.x, wid = tid >> 5, lane = tid & 31;
    int mw = wid & 3, nh = wid >> 2;

    if (TRANS && tid < 32)
        ((float4*)sbias)[tid] = ((const float4*)bias_in)[tid];
    for (int i = tid; i < (2 * WIMG_HALF * 2) / 16; i += 256)
        ((uint4*)sW)[i] = ((const uint4*)Wimg)[i];
    __syncthreads();

    uint32_t aHiBase = smem_u32(sAhi) + (mw * 16 + (lane & 15)) * (WSTRIDE * 2)
                     + (lane >> 4) * 16;
    uint32_t aLoBase = aHiBase + TILE_M * WSTRIDE * 2;
    uint32_t bBase = smem_u32(sW) + (lane & 15) * (WSTRIDE * 2) + nh * 128;

    for (int t = blockIdx.x; t < ntiles; t += gridDim.x) {
        int r0 = t * TILE_M;
        convert_tile64<TRANS>(X, sbias, sAhi, sAlo, r0, nrows);
        __syncthreads();

        float acc[8][4];
#pragma unroll
        for (int nt = 0; nt < 8; nt++)
#pragma unroll
            for (int q = 0; q < 4; q++) acc[nt][q] = 0.f;

        // Pass A-hi: Ah@Wh + Ah@Wl (one A frag feeds both W halves)
#pragma unroll 1
        for (int ks = 0; ks < 8; ks++) {
            uint32_t a0, a1, a2, a3;
            ldm_x4(a0, a1, a2, a3, aHiBase + ks * 32);
            uint32_t bk = bBase + ks * 16 * (WSTRIDE * 2);
#pragma unroll
            for (int nt = 0; nt < 8; nt++) {
                uint32_t b0, b1, c0, c1;
                ldm_x2t(b0, b1, bk + nt * 16);
                mma_bf16(acc[nt], a0, a1, a2, a3, b0, b1);
                ldm_x2t(c0, c1, bk + nt * 16 + WIMG_HALF * 2);
                mma_bf16(acc[nt], a0, a1, a2, a3, c0, c1);
            }
        }
        // Pass A-lo: Al@Wh
#pragma unroll 1
        for (int ks = 0; ks < 8; ks++) {
            uint32_t a0, a1, a2, a3;
            ldm_x4(a0, a1, a2, a3, aLoBase + ks * 32);
            uint32_t bk = bBase + ks * 16 * (WSTRIDE * 2);
#pragma unroll
            for (int nt = 0; nt < 8; nt++) {
                uint32_t b0, b1;
                ldm_x2t(b0, b1, bk + nt * 16);
                mma_bf16(acc[nt], a0, a1, a2, a3, b0, b1);
            }
        }

        // Epilogue: H' = dinv[row] * result
        int row0 = r0 + mw * 16 + (lane >> 2);
        int colb = nh * 64 + (lane & 3) * 2;
#pragma unroll
        for (int half = 0; half < 2; half++) {
            int row = row0 + half * 8;
            if (row < nrows) {
                float dv = dinv[row];
                float* po = Hs + (size_t)row * 128 + colb;
#pragma unroll
                for (int nt = 0; nt < 8; nt++)
                    *(float2*)(po + nt * 8) =
                        make_float2(acc[nt][2 * half] * dv, acc[nt][2 * half + 1] * dv);
            }
        }
        __syncthreads();  // protect sA before next tile's convert
    }
}

// ---------------------------------------------------------------------------
// CSR gather: AGG[n] = dinv[n] * (H'[n] + sum_{s in in(n)} H'[s])
// Warp per node, 4-way edge unroll. No per-edge dinv loads.
// ---------------------------------------------------------------------------
__global__ void gather_k(const float* __restrict__ Hs,
                         const int* __restrict__ rowptr,
                         const int* __restrict__ col,
                         const float* __restrict__ dinv,
                         float* __restrict__ AGG) {
    int gtid = blockIdx.x * blockDim.x + threadIdx.x;
    int lane = gtid & 31;
    int w = gtid >> 5;
    int nw = (gridDim.x * blockDim.x) >> 5;
    for (int n = w; n < NN; n += nw) {
        float4 a0 = reinterpret_cast<const float4*>(Hs + (size_t)n * 128)[lane];
        float4 a1 = make_float4(0.f, 0.f, 0.f, 0.f), a2 = a1, a3 = a1;
        int j = rowptr[n];
        int end = rowptr[n + 1];
        for (; j + 3 < end; j += 4) {
            int s0 = __ldg(&col[j]);
            int s1 = __ldg(&col[j + 1]);
            int s2 = __ldg(&col[j + 2]);
            int s3 = __ldg(&col[j + 3]);
            float4 v0 = reinterpret_cast<const float4*>(Hs + (size_t)s0 * 128)[lane];
            float4 v1 = reinterpret_cast<const float4*>(Hs + (size_t)s1 * 128)[lane];
            float4 v2 = reinterpret_cast<const float4*>(Hs + (size_t)s2 * 128)[lane];
            float4 v3 = reinterpret_cast<const float4*>(Hs + (size_t)s3 * 128)[lane];
            a0.x += v0.x; a0.y += v0.y; a0.z += v0.z; a0.w += v0.w;
            a1.x += v1.x; a1.y += v1.y; a1.z += v1.z; a1.w += v1.w;
            a2.x += v2.x; a2.y += v2.y; a2.z += v2.z; a2.w += v2.w;
            a3.x += v3.x; a3.y += v3.y; a3.z += v3.z; a3.w += v3.w;
        }
        for (; j < end; j++) {
            int s0 = __ldg(&col[j]);
            float4 v0 = reinterpret_cast<const float4*>(Hs + (size_t)s0 * 128)[lane];
            a0.x += v0.x; a0.y += v0.y; a0.z += v0.z; a0.w += v0.w;
        }
        float dn = dinv[n];
        a0.x = (a0.x + a1.x + a2.x + a3.x) * dn;
        a0.y = (a0.y + a1.y + a2.y + a3.y) * dn;
        a0.z = (a0.z + a1.z + a2.z + a3.z) * dn;
        a0.w = (a0.w + a1.w + a2.w + a3.w) * dn;
        reinterpret_cast<float4*>(AGG + (size_t)n * 128)[lane] = a0;
    }
}

// ---------------------------------------------------------------------------
// Pair dot products: out[p] = dot(H[a]+b2, H[b]+b2).  2 pairs per warp iter.
// ---------------------------------------------------------------------------
__global__ void pairs_k(const float* __restrict__ H,
                        const float* __restrict__ b2,
                        const int* __restrict__ ep,
                        const int* __restrict__ en,
                        float* __restrict__ out) {
    int gtid = blockIdx.x * blockDim.x + threadIdx.x;
    int lane = gtid & 31;
    int warp = gtid >> 5;
    int nwarps = (gridDim.x * blockDim.x) >> 5;
    const int total = 2 * NP;
    float4 bv = reinterpret_cast<const float4*>(b2)[lane];
    for (int p = warp * 2; p < total; p += nwarps * 2) {
        const int* e0 = (p < NP) ? (ep + 2 * (size_t)p)
                                 : (en + 2 * (size_t)(p - NP));
        int p1 = p + 1;
        const int* e1 = (p1 < NP) ? (ep + 2 * (size_t)p1)
                                  : (en + 2 * (size_t)(p1 - NP));
        int a = e0[0], b = e0[1];
        int c = e1[0], d = e1[1];
        float4 va = reinterpret_cast<const float4*>(H + (size_t)a * 128)[lane];
        float4 vb = reinterpret_cast<const float4*>(H + (size_t)b * 128)[lane];
        float4 vc = reinterpret_cast<const float4*>(H + (size_t)c * 128)[lane];
        float4 vd = reinterpret_cast<const float4*>(H + (size_t)d * 128)[lane];
        va.x += bv.x; va.y += bv.y; va.z += bv.z; va.w += bv.w;
        vb.x += bv.x; vb.y += bv.y; vb.z += bv.z; vb.w += bv.w;
        vc.x += bv.x; vc.y += bv.y; vc.z += bv.z; vc.w += bv.w;
        vd.x += bv.x; vd.y += bv.y; vd.z += bv.z; vd.w += bv.w;
        float s0 = va.x * vb.x + va.y * vb.y + va.z * vb.z + va.w * vb.w;
        float s1 = vc.x * vd.x + vc.y * vd.y + vc.z * vd.z + vc.w * vd.w;
#pragma unroll
        for (int o = 16; o; o >>= 1) {
            s0 += __shfl_xor_sync(0xffffffffu, s0, o);
            s1 += __shfl_xor_sync(0xffffffffu, s1, o);
        }
        if (lane == 0) { out[p] = s0; out[p1] = s1; }
    }
}

// ---------------------------------------------------------------------------
// Launch
// ---------------------------------------------------------------------------
extern "C" void kernel_launch(void* const* d_in, const int* in_sizes, int n_in,
                              void* d_out, int out_size) {
    const float* x  = (const float*)d_in[0];
    const float* W1 = (const float*)d_in[1];
    const float* b1 = (const float*)d_in[2];
    const float* W2 = (const float*)d_in[3];
    const float* b2 = (const float*)d_in[4];
    const int* edge_index = (const int*)d_in[5];
    const int* edges      = (const int*)d_in[6];
    const int* edges_neg  = (const int*)d_in[7];
    float* out = (float*)d_out;

    const int* src = edge_index;
    const int* dst = edge_index + NE;

    float *bufA, *bufB, *dinv;
    int *deg, *rowptr, *cursor, *col, *bsum, *boff;
    __nv_bfloat16* wimg;
    cudaGetSymbolAddress((void**)&bufA,   g_bufA);
    cudaGetSymbolAddress((void**)&bufB,   g_bufB);
    cudaGetSymbolAddress((void**)&deg,    g_deg);
    cudaGetSymbolAddress((void**)&dinv,   g_dinv);
    cudaGetSymbolAddress((void**)&rowptr, g_rowptr);
    cudaGetSymbolAddress((void**)&cursor, g_cursor);
    cudaGetSymbolAddress((void**)&col,    g_col);
    cudaGetSymbolAddress((void**)&bsum,   g_bsum);
    cudaGetSymbolAddress((void**)&boff,   g_boff);
    cudaGetSymbolAddress((void**)&wimg,   g_Wimg);

    const int SMEM_MMA = 512 + 2 * WIMG_HALF * 2 + 2 * TILE_M * WSTRIDE * 2;  // 104960
    cudaFuncSetAttribute(gemm_mma_k<false>, cudaFuncAttributeMaxDynamicSharedMemorySize, SMEM_MMA);
    cudaFuncSetAttribute(gemm_mma_k<true>,  cudaFuncAttributeMaxDynamicSharedMemorySize, SMEM_MMA);

    // 1. degree + normalization + W split
    init_deg_k<<<(NN + 255) / 256, 256>>>(deg);
    count_deg_k<<<4096, 256>>>(dst, deg);
    dinv_k<<<(NN + 255) / 256, 256>>>(deg, dinv);
    wsplit_k<<<(2 * WIMG_HALF + 255) / 256, 256>>>(W1, W2, wimg);

    // 2. CSR build (once; shared by both layers)
    scan1_k<<<NBLK, SCAN_B>>>(deg, bsum);
    scan2_k<<<1, 256>>>(bsum, boff);
    scan3_k<<<NBLK, SCAN_B>>>(deg, boff, rowptr, cursor);
    fill_k<<<4096, 256>>>(src, dst, cursor, col);

    const int ntiles = (NN + TILE_M - 1) / TILE_M;  // 1563

    // 3. layer 1: H1' = dinv * (x @ W1);  AGG1 = dinv * (sum + self)
    gemm_mma_k<false><<<GEMM_GRID, 256, SMEM_MMA>>>(x, wimg, nullptr, bufA, dinv, NN, ntiles);
    gather_k<<<12500, 256>>>(bufA, rowptr, col, dinv, bufB);

    // 4. layer 2: H2' = dinv * (relu(AGG1 + b1) @ W2);  AGG2 likewise
    gemm_mma_k<true><<<GEMM_GRID, 256, SMEM_MMA>>>(bufB, wimg + WIMG_LAYER, b1, bufA, dinv, NN, ntiles);
    gather_k<<<12500, 256>>>(bufA, rowptr, col, dinv, bufB);

    // 5. pair dots (b2 added on the fly)
    pairs_k<<<8192, 256>>>(bufB, b2, edges, edges_neg, out);
}

// round 11
// speedup vs baseline: 1.8893x; 1.0045x over previous
#include <cuda_runtime.h>
#include <cuda_bf16.h>
#include <cuda_fp16.h>
#include <cstdint>

#define NN 100000
#define NE 1600000
#define NP 500000
#define DD 128
#define SCAN_B 512
#define NBLK ((NN + SCAN_B - 1) / SCAN_B)   // 196

#define WSTRIDE 136                  // bf16 elems per padded row (272 B)
#define WIMG_HALF (128 * WSTRIDE)    // 17408 elems per hi/lo image
#define WIMG_LAYER (2 * WIMG_HALF)   // 34816 elems (hi+lo) per layer
#define TILE_M 64
#define GEMM_GRID 296                // 2 CTAs/SM x 148 SMs (persistent)

// Scratch (device globals: allocation-free rule)
__device__ float g_bufA[(size_t)NN * DD];   // H' as fp16 lives in low half
__device__ float g_bufB[(size_t)NN * DD];   // AGG1 fp32 / G16 fp16
__device__ int   g_deg[NN];
__device__ float g_dinv[NN];
__device__ int   g_rowptr[NN + 1];
__device__ int   g_cursor[NN];
__device__ int   g_col[NE];
__device__ int   g_bsum[NBLK];
__device__ int   g_boff[NBLK];
__device__ __align__(16) __nv_bfloat16 g_Wimg[2 * WIMG_LAYER];  // 139 KB

// ===========================================================================
// mma.sync / ldmatrix helpers (base ISA, works on compute_103 target)
// ===========================================================================
__device__ __forceinline__ uint32_t smem_u32(const void* p) {
    uint32_t a;
    asm("{ .reg .u64 t; cvta.to.shared.u64 t, %1; cvt.u32.u64 %0, t; }"
        : "=r"(a) : "l"(p));
    return a;
}
__device__ __forceinline__ void ldm_x4(uint32_t& r0, uint32_t& r1,
                                       uint32_t& r2, uint32_t& r3, uint32_t addr) {
    asm volatile("ldmatrix.sync.aligned.m8n8.x4.shared.b16 {%0,%1,%2,%3}, [%4];"
                 : "=r"(r0), "=r"(r1), "=r"(r2), "=r"(r3) : "r"(addr));
}
__device__ __forceinline__ void ldm_x2t(uint32_t& r0, uint32_t& r1, uint32_t addr) {
    asm volatile("ldmatrix.sync.aligned.m8n8.x2.trans.shared.b16 {%0,%1}, [%2];"
                 : "=r"(r0), "=r"(r1) : "r"(addr));
}
__device__ __forceinline__ void mma_bf16(float* c, uint32_t a0, uint32_t a1,
                                         uint32_t a2, uint32_t a3,
                                         uint32_t b0, uint32_t b1) {
    asm volatile(
        "mma.sync.aligned.m16n8k16.row.col.f32.bf16.bf16.f32 "
        "{%0,%1,%2,%3}, {%4,%5,%6,%7}, {%8,%9}, {%0,%1,%2,%3};"
        : "+f"(c[0]), "+f"(c[1]), "+f"(c[2]), "+f"(c[3])
        : "r"(a0), "r"(a1), "r"(a2), "r"(a3), "r"(b0), "r"(b1));
}
__device__ __forceinline__ float4 h4_to_f4(uint2 u) {
    __half2 h0 = *(__half2*)&u.x;
    __half2 h1 = *(__half2*)&u.y;
    float2 f0 = __half22float2(h0);
    float2 f1 = __half22float2(h1);
    return make_float4(f0.x, f0.y, f1.x, f1.y);
}

// ---------------------------------------------------------------------------
// Degree / normalization
// ---------------------------------------------------------------------------
__global__ void init_deg_k(int* __restrict__ deg) {
    int i = blockIdx.x * blockDim.x + threadIdx.x;
    if (i < NN) deg[i] = 1;  // self loop
}

__global__ void count_deg_k(const int* __restrict__ dst, int* __restrict__ deg) {
    int i = blockIdx.x * blockDim.x + threadIdx.x;
    int stride = gridDim.x * blockDim.x;
    for (int e = i; e < NE; e += stride)
        atomicAdd(&deg[dst[e]], 1);
}

__global__ void dinv_k(const int* __restrict__ deg, float* __restrict__ dinv) {
    int i = blockIdx.x * blockDim.x + threadIdx.x;
    if (i < NN) dinv[i] = rsqrtf((float)deg[i]);
}

// ---------------------------------------------------------------------------
// W split: W[k][n] fp32 -> k-major bf16 images [128][WSTRIDE] hi then lo.
// ---------------------------------------------------------------------------
__global__ void wsplit_k(const float* __restrict__ W1, const float* __restrict__ W2,
                         __nv_bfloat16* __restrict__ img) {
    int i = blockIdx.x * blockDim.x + threadIdx.x;
    if (i >= 2 * WIMG_HALF) return;
    int L = i / WIMG_HALF;
    int rem = i % WIMG_HALF;
    int k = rem / WSTRIDE;
    int n = rem % WSTRIDE;
    const float* W = L ? W2 : W1;
    float v = (n < 128) ? W[k * 128 + n] : 0.f;
    __nv_bfloat16 h = __float2bfloat16(v);
    __nv_bfloat16 l = __float2bfloat16(v - __bfloat162float(h));
    img[(size_t)L * WIMG_LAYER + rem] = h;
    img[(size_t)L * WIMG_LAYER + WIMG_HALF + rem] = l;
}

// ---------------------------------------------------------------------------
// CSR build
// ---------------------------------------------------------------------------
__global__ void scan1_k(const int* __restrict__ deg, int* __restrict__ bsum) {
    __shared__ int s[SCAN_B];
    int t = threadIdx.x;
    int i = blockIdx.x * SCAN_B + t;
    s[t] = (i < NN) ? (deg[i] - 1) : 0;
    __syncthreads();
    for (int off = SCAN_B / 2; off > 0; off >>= 1) {
        if (t < off) s[t] += s[t + off];
        __syncthreads();
    }
    if (t == 0) bsum[blockIdx.x] = s[0];
}

__global__ void scan2_k(const int* __restrict__ bsum, int* __restrict__ boff) {
    __shared__ int s[NBLK];
    int t = threadIdx.x;
    for (int i = t; i < NBLK; i += blockDim.x) s[i] = bsum[i];
    __syncthreads();
    if (t == 0) {
        int run = 0;
        for (int b = 0; b < NBLK; b++) { int v = s[b]; s[b] = run; run += v; }
    }
    __syncthreads();
    for (int i = t; i < NBLK; i += blockDim.x) boff[i] = s[i];
}

__global__ void scan3_k(const int* __restrict__ deg, const int* __restrict__ boff,
                        int* __restrict__ rowptr, int* __restrict__ cursor) {
    __shared__ int s[2][SCAN_B];
    int t = threadIdx.x;
    int i = blockIdx.x * SCAN_B + t;
    int v = (i < NN) ? (deg[i] - 1) : 0;
    s[0][t] = v;
    __syncthreads();
    int pp = 0;
    for (int off = 1; off < SCAN_B; off <<= 1) {
        int nv = s[pp][t] + ((t >= off) ? s[pp][t - off] : 0);
        s[1 - pp][t] = nv;
        pp = 1 - pp;
        __syncthreads();
    }
    if (i < NN) {
        int excl = s[pp][t] - v + boff[blockIdx.x];
        rowptr[i] = excl;
        cursor[i] = excl;
        if (i == NN - 1) rowptr[NN] = excl + v;
    }
}

__global__ void fill_k(const int* __restrict__ src, const int* __restrict__ dst,
                       int* __restrict__ cursor, int* __restrict__ col) {
    int i = blockIdx.x * blockDim.x + threadIdx.x;
    int stride = gridDim.x * blockDim.x;
    for (int e = i; e < NE; e += stride) {
        int d = dst[e];
        int pos = atomicAdd(&cursor[d], 1);
        col[pos] = src[e];
    }
}

// ---------------------------------------------------------------------------
// Convert TILE_M fp32 rows -> bf16 hi AND lo images in one pass.
// ---------------------------------------------------------------------------
template <bool TRANS>
__device__ __forceinline__ void convert_tile64(const float* __restrict__ X,
                                               const float* __restrict__ sbias,
                                               __nv_bfloat16* __restrict__ sAhi,
                                               __nv_bfloat16* __restrict__ sAlo,
                                               int r0, int nrows) {
    int tid = threadIdx.x;
    int m = tid >> 2;
    int c0 = (tid & 3) << 5;
    long r = (long)r0 + m;
    bool valid = r < nrows;
    const float4* Xv = (const float4*)(X + (size_t)r * 128 + c0);
    const float4* Bv = (const float4*)(sbias + c0);
    uint4* dh = (uint4*)(sAhi + m * WSTRIDE + c0);
    uint4* dl = (uint4*)(sAlo + m * WSTRIDE + c0);
#pragma unroll
    for (int j = 0; j < 4; j++) {
        float4 v0 = make_float4(0.f, 0.f, 0.f, 0.f), v1 = v0;
        if (valid) { v0 = Xv[2 * j]; v1 = Xv[2 * j + 1]; }
        if (TRANS) {
            float4 b0 = Bv[2 * j], b1 = Bv[2 * j + 1];
            v0.x = fmaxf(v0.x + b0.x, 0.f); v0.y = fmaxf(v0.y + b0.y, 0.f);
            v0.z = fmaxf(v0.z + b0.z, 0.f); v0.w = fmaxf(v0.w + b0.w, 0.f);
            v1.x = fmaxf(v1.x + b1.x, 0.f); v1.y = fmaxf(v1.y + b1.y, 0.f);
            v1.z = fmaxf(v1.z + b1.z, 0.f); v1.w = fmaxf(v1.w + b1.w, 0.f);
        }
        float f[8] = {v0.x, v0.y, v0.z, v0.w, v1.x, v1.y, v1.z, v1.w};
        uint32_t ph[4], pl[4];
#pragma unroll
        for (int q = 0; q < 4; q++) {
            float a = f[2 * q], b = f[2 * q + 1];
            __nv_bfloat16 ha = __float2bfloat16(a);
            __nv_bfloat16 hb = __float2bfloat16(b);
            __nv_bfloat16 la = __float2bfloat16(a - __bfloat162float(ha));
            __nv_bfloat16 lb = __float2bfloat16(b - __bfloat162float(hb));
            __nv_bfloat162 th; th.x = ha; th.y = hb;
            __nv_bfloat162 tl; tl.x = la; tl.y = lb;
            ph[q] = *(uint32_t*)&th;
            pl[q] = *(uint32_t*)&tl;
        }
        dh[j] = make_uint4(ph[0], ph[1], ph[2], ph[3]);
        dl[j] = make_uint4(pl[0], pl[1], pl[2], pl[3]);
    }
}

// ---------------------------------------------------------------------------
// Persistent HMMA GEMM: Hs16[N,128] = fp16( dinv * (f(X) @ W) ), 2-way bf16
// split input. W loaded to smem ONCE per block; loops over 64-row tiles.
// ---------------------------------------------------------------------------
template <bool TRANS>
__global__ void __launch_bounds__(256) gemm_mma_k(const float* __restrict__ X,
                                                  const __nv_bfloat16* __restrict__ Wimg,
                                                  const float* __restrict__ bias_in,
                                                  __half* __restrict__ Hs,
                                                  const float* __restrict__ dinv,
                                                  int nrows, int ntiles) {
    extern __shared__ __align__(16) unsigned char sm[];
    float* sbias = (float*)sm;                                    // 512 B
    __nv_bfloat16* sW   = (__nv_bfloat16*)(sm + 512);             // hi then lo
    __nv_bfloat16* sAhi = (__nv_bfloat16*)(sm + 512 + 2 * WIMG_HALF * 2);
    __nv_bfloat16* sAlo = sAhi + TILE_M * WSTRIDE;
    int tid = threadIdx.x, wid = tid >> 5, lane = tid & 31;
    int mw = wid & 3, nh = wid >> 2;

    if (TRANS && tid < 32)
        ((float4*)sbias)[tid] = ((const float4*)bias_in)[tid];
    for (int i = tid; i < (2 * WIMG_HALF * 2) / 16; i += 256)
        ((uint4*)sW)[i] = ((const uint4*)Wimg)[i];
    __syncthreads();

    uint32_t aHiBase = smem_u32(sAhi) + (mw * 16 + (lane & 15)) * (WSTRIDE * 2)
                     + (lane >> 4) * 16;
    uint32_t aLoBase = aHiBase + TILE_M * WSTRIDE * 2;
    uint32_t bBase = smem_u32(sW) + (lane & 15) * (WSTRIDE * 2) + nh * 128;

    for (int t = blockIdx.x; t < ntiles; t += gridDim.x) {
        int r0 = t * TILE_M;
        convert_tile64<TRANS>(X, sbias, sAhi, sAlo, r0, nrows);
        __syncthreads();

        float acc[8][4];
#pragma unroll
        for (int nt = 0; nt < 8; nt++)
#pragma unroll
            for (int q = 0; q < 4; q++) acc[nt][q] = 0.f;

#pragma unroll 1
        for (int ks = 0; ks < 8; ks++) {
            uint32_t a0, a1, a2, a3;
            ldm_x4(a0, a1, a2, a3, aHiBase + ks * 32);
            uint32_t bk = bBase + ks * 16 * (WSTRIDE * 2);
#pragma unroll
            for (int nt = 0; nt < 8; nt++) {
                uint32_t b0, b1, c0, c1;
                ldm_x2t(b0, b1, bk + nt * 16);
                mma_bf16(acc[nt], a0, a1, a2, a3, b0, b1);
                ldm_x2t(c0, c1, bk + nt * 16 + WIMG_HALF * 2);
                mma_bf16(acc[nt], a0, a1, a2, a3, c0, c1);
            }
        }
#pragma unroll 1
        for (int ks = 0; ks < 8; ks++) {
            uint32_t a0, a1, a2, a3;
            ldm_x4(a0, a1, a2, a3, aLoBase + ks * 32);
            uint32_t bk = bBase + ks * 16 * (WSTRIDE * 2);
#pragma unroll
            for (int nt = 0; nt < 8; nt++) {
                uint32_t b0, b1;
                ldm_x2t(b0, b1, bk + nt * 16);
                mma_bf16(acc[nt], a0, a1, a2, a3, b0, b1);
            }
        }

        // Epilogue: H' = fp16(dinv[row] * result)
        int row0 = r0 + mw * 16 + (lane >> 2);
        int colb = nh * 64 + (lane & 3) * 2;
#pragma unroll
        for (int half = 0; half < 2; half++) {
            int row = row0 + half * 8;
            if (row < nrows) {
                float dv = dinv[row];
                __half* po = Hs + (size_t)row * 128 + colb;
#pragma unroll
                for (int nt = 0; nt < 8; nt++)
                    *(__half2*)(po + nt * 8) =
                        __floats2half2_rn(acc[nt][2 * half] * dv,
                                          acc[nt][2 * half + 1] * dv);
            }
        }
        __syncthreads();  // protect sA before next tile's convert
    }
}

// ---------------------------------------------------------------------------
// CSR gather: sum = H'[n] + sum_{s in in(n)} H'[s]  (fp16 reads, fp32 accum)
// OUT_HALF=false: AGG fp32 = dinv[n]*sum         (feeds gemm2)
// OUT_HALF=true:  G16 fp16 = dinv[n]*sum + b2    (feeds pairs)
// Warp per node, lane owns 4 columns (8 B fp16), 4-way edge unroll.
// ---------------------------------------------------------------------------
template <bool OUT_HALF>
__global__ void gather_k(const __half* __restrict__ Hs,
                         const int* __restrict__ rowptr,
                         const int* __restrict__ col,
                         const float* __restrict__ dinv,
                         const float* __restrict__ b2,
                         void* __restrict__ OUTP) {
    int gtid = blockIdx.x * blockDim.x + threadIdx.x;
    int lane = gtid & 31;
    int w = gtid >> 5;
    int nw = (gridDim.x * blockDim.x) >> 5;
    float4 bv = make_float4(0.f, 0.f, 0.f, 0.f);
    if (OUT_HALF) bv = ((const float4*)b2)[lane];
    for (int n = w; n < NN; n += nw) {
        float4 a0 = h4_to_f4(((const uint2*)(Hs + (size_t)n * 128))[lane]);
        float4 a1 = make_float4(0.f, 0.f, 0.f, 0.f), a2 = a1, a3 = a1;
        int j = rowptr[n];
        int end = rowptr[n + 1];
        for (; j + 3 < end; j += 4) {
            int s0 = __ldg(&col[j]);
            int s1 = __ldg(&col[j + 1]);
            int s2 = __ldg(&col[j + 2]);
            int s3 = __ldg(&col[j + 3]);
            float4 v0 = h4_to_f4(((const uint2*)(Hs + (size_t)s0 * 128))[lane]);
            float4 v1 = h4_to_f4(((const uint2*)(Hs + (size_t)s1 * 128))[lane]);
            float4 v2 = h4_to_f4(((const uint2*)(Hs + (size_t)s2 * 128))[lane]);
            float4 v3 = h4_to_f4(((const uint2*)(Hs + (size_t)s3 * 128))[lane]);
            a0.x += v0.x; a0.y += v0.y; a0.z += v0.z; a0.w += v0.w;
            a1.x += v1.x; a1.y += v1.y; a1.z += v1.z; a1.w += v1.w;
            a2.x += v2.x; a2.y += v2.y; a2.z += v2.z; a2.w += v2.w;
            a3.x += v3.x; a3.y += v3.y; a3.z += v3.z; a3.w += v3.w;
        }
        for (; j < end; j++) {
            int s0 = __ldg(&col[j]);
            float4 v0 = h4_to_f4(((const uint2*)(Hs + (size_t)s0 * 128))[lane]);
            a0.x += v0.x; a0.y += v0.y; a0.z += v0.z; a0.w += v0.w;
        }
        float dn = dinv[n];
        a0.x = (a0.x + a1.x + a2.x + a3.x) * dn;
        a0.y = (a0.y + a1.y + a2.y + a3.y) * dn;
        a0.z = (a0.z + a1.z + a2.z + a3.z) * dn;
        a0.w = (a0.w + a1.w + a2.w + a3.w) * dn;
        if (OUT_HALF) {
            a0.x += bv.x; a0.y += bv.y; a0.z += bv.z; a0.w += bv.w;
            uint2 u;
            *(__half2*)&u.x = __floats2half2_rn(a0.x, a0.y);
            *(__half2*)&u.y = __floats2half2_rn(a0.z, a0.w);
            ((uint2*)((__half*)OUTP + (size_t)n * 128))[lane] = u;
        } else {
            ((float4*)((float*)OUTP + (size_t)n * 128))[lane] = a0;
        }
    }
}

// ---------------------------------------------------------------------------
// Pair dot products on fp16 G (bias pre-added): out[p] = dot(G[a], G[b])
// 2 pairs per warp iteration; lane owns 4 columns (8 B per row read).
// ---------------------------------------------------------------------------
__global__ void pairs_k(const __half* __restrict__ G,
                        const int* __restrict__ ep,
                        const int* __restrict__ en,
                        float* __restrict__ out) {
    int gtid = blockIdx.x * blockDim.x + threadIdx.x;
    int lane = gtid & 31;
    int warp = gtid >> 5;
    int nwarps = (gridDim.x * blockDim.x) >> 5;
    const int total = 2 * NP;
    for (int p = warp * 2; p < total; p += nwarps * 2) {
        const int* e0 = (p < NP) ? (ep + 2 * (size_t)p)
                                 : (en + 2 * (size_t)(p - NP));
        int p1 = p + 1;
        const int* e1 = (p1 < NP) ? (ep + 2 * (size_t)p1)
                                  : (en + 2 * (size_t)(p1 - NP));
        int a = e0[0], b = e0[1];
        int c = e1[0], d = e1[1];
        float4 va = h4_to_f4(((const uint2*)(G + (size_t)a * 128))[lane]);
        float4 vb = h4_to_f4(((const uint2*)(G + (size_t)b * 128))[lane]);
        float4 vc = h4_to_f4(((const uint2*)(G + (size_t)c * 128))[lane]);
        float4 vd = h4_to_f4(((const uint2*)(G + (size_t)d * 128))[lane]);
        float s0 = va.x * vb.x + va.y * vb.y + va.z * vb.z + va.w * vb.w;
        float s1 = vc.x * vd.x + vc.y * vd.y + vc.z * vd.z + vc.w * vd.w;
#pragma unroll
        for (int o = 16; o; o >>= 1) {
            s0 += __shfl_xor_sync(0xffffffffu, s0, o);
            s1 += __shfl_xor_sync(0xffffffffu, s1, o);
        }
        if (lane == 0) { out[p] = s0; out[p1] = s1; }
    }
}

// ---------------------------------------------------------------------------
// Launch
// ---------------------------------------------------------------------------
extern "C" void kernel_launch(void* const* d_in, const int* in_sizes, int n_in,
                              void* d_out, int out_size) {
    const float* x  = (const float*)d_in[0];
    const float* W1 = (const float*)d_in[1];
    const float* b1 = (const float*)d_in[2];
    const float* W2 = (const float*)d_in[3];
    const float* b2 = (const float*)d_in[4];
    const int* edge_index = (const int*)d_in[5];
    const int* edges      = (const int*)d_in[6];
    const int* edges_neg  = (const int*)d_in[7];
    float* out = (float*)d_out;

    const int* src = edge_index;
    const int* dst = edge_index + NE;

    float *bufA, *bufB, *dinv;
    int *deg, *rowptr, *cursor, *col, *bsum, *boff;
    __nv_bfloat16* wimg;
    cudaGetSymbolAddress((void**)&bufA,   g_bufA);
    cudaGetSymbolAddress((void**)&bufB,   g_bufB);
    cudaGetSymbolAddress((void**)&deg,    g_deg);
    cudaGetSymbolAddress((void**)&dinv,   g_dinv);
    cudaGetSymbolAddress((void**)&rowptr, g_rowptr);
    cudaGetSymbolAddress((void**)&cursor, g_cursor);
    cudaGetSymbolAddress((void**)&col,    g_col);
    cudaGetSymbolAddress((void**)&bsum,   g_bsum);
    cudaGetSymbolAddress((void**)&boff,   g_boff);
    cudaGetSymbolAddress((void**)&wimg,   g_Wimg);

    __half* hA = (__half*)bufA;   // H' fp16 image
    __half* gB = (__half*)bufB;   // G16 fp16 image (pairs input)

    const int SMEM_MMA = 512 + 2 * WIMG_HALF * 2 + 2 * TILE_M * WSTRIDE * 2;  // 104960
    cudaFuncSetAttribute(gemm_mma_k<false>, cudaFuncAttributeMaxDynamicSharedMemorySize, SMEM_MMA);
    cudaFuncSetAttribute(gemm_mma_k<true>,  cudaFuncAttributeMaxDynamicSharedMemorySize, SMEM_MMA);

    // 1. degree + normalization + W split
    init_deg_k<<<(NN + 255) / 256, 256>>>(deg);
    count_deg_k<<<4096, 256>>>(dst, deg);
    dinv_k<<<(NN + 255) / 256, 256>>>(deg, dinv);
    wsplit_k<<<(2 * WIMG_HALF + 255) / 256, 256>>>(W1, W2, wimg);

    // 2. CSR build (once; shared by both layers)
    scan1_k<<<NBLK, SCAN_B>>>(deg, bsum);
    scan2_k<<<1, 256>>>(bsum, boff);
    scan3_k<<<NBLK, SCAN_B>>>(deg, boff, rowptr, cursor);
    fill_k<<<4096, 256>>>(src, dst, cursor, col);

    const int ntiles = (NN + TILE_M - 1) / TILE_M;  // 1563

    // 3. layer 1: H1' = fp16(dinv * (x @ W1));  AGG1 fp32
    gemm_mma_k<false><<<GEMM_GRID, 256, SMEM_MMA>>>(x, wimg, nullptr, hA, dinv, NN, ntiles);
    gather_k<false><<<12500, 256>>>(hA, rowptr, col, dinv, b2, bufB);

    // 4. layer 2: H2' = fp16(dinv * (relu(AGG1 + b1) @ W2));  G16 = AGG2 + b2
    gemm_mma_k<true><<<GEMM_GRID, 256, SMEM_MMA>>>(bufB, wimg + WIMG_LAYER, b1, hA, dinv, NN, ntiles);
    gather_k<true><<<12500, 256>>>(hA, rowptr, col, dinv, b2, gB);

    // 5. pair dots on fp16 G
    pairs_k<<<8192, 256>>>(gB, edges, edges_neg, out);
}